// round 7
// baseline (speedup 1.0000x reference)
#include <cuda_runtime.h>
#include <math.h>
#include <stdint.h>

#define NDIM  4096
#define BDIM  512
#define B2R   1024
#define EPSV  1.0f
#define LAMDA 10.0f

// ---------------- scratch (static device globals; no allocation) -------------
__device__ float g_K32[NDIM * NDIM];   // K pre-rounded to tf32 bit patterns (64MB)
__device__ float g_B2 [NDIM * B2R ];   // [4096][1024]: cols 0..511 = f, 512..1023 = f*flog (tf32)
__device__ float g_C  [NDIM * B2R ];   // [4096][1024]: cols 0..511 = Kf, 512..1023 = K@(f*flog)
__device__ float g_a  [NDIM * BDIM];   // a = P / Kf (tf32-rounded)  [4096][512]
__device__ float g_KTa[NDIM * BDIM];   // K^T @ a      [4096][512]
__device__ float g_p1[NDIM], g_p2[NDIM], g_p3[NDIM], g_p4[NDIM];

// ---------------- helpers -----------------------------------------------------
__device__ __forceinline__ uint32_t smem_u32(const void* p) {
    return (uint32_t)__cvta_generic_to_shared(p);
}
__device__ __forceinline__ void cpasync16(uint32_t dst, const void* src) {
    asm volatile("cp.async.cg.shared.global [%0], [%1], 16;"
                 :: "r"(dst), "l"(src) : "memory");
}
__device__ __forceinline__ float tf32r(float x) {
    uint32_t r;
    asm("cvt.rna.tf32.f32 %0, %1;" : "=r"(r) : "f"(x));
    return __uint_as_float(r);
}
__device__ __forceinline__ void mma_tf32(float* c, const uint32_t* a, const uint32_t* b) {
    asm volatile(
        "mma.sync.aligned.m16n8k8.row.col.f32.tf32.tf32.f32 "
        "{%0,%1,%2,%3}, {%4,%5,%6,%7}, {%8,%9}, {%0,%1,%2,%3};"
        : "+f"(c[0]), "+f"(c[1]), "+f"(c[2]), "+f"(c[3])
        : "r"(a[0]), "r"(a[1]), "r"(a[2]), "r"(a[3]), "r"(b[0]), "r"(b[1]));
}

// ---------------- tensor-core tf32 GEMM ---------------------------------------
// C[4096, ncols] = op(K32)[4096,4096] @ B[4096, ncols]; all inputs pre-rounded tf32.
// BM=128, BN=64, 128 threads (2x2 warps, warp tile 64x32), 3-stage cp.async.
#define STAGES 3
#define BKT 16

template <bool TRANSA>
__global__ void __launch_bounds__(128, 4)
gemm_mma(const float* __restrict__ A, const float* __restrict__ B,
         float* __restrict__ C, int ncols)
{
    extern __shared__ float sm[];
    constexpr int AST = TRANSA ? 136 : 20;
    constexpr int ASZ = TRANSA ? (BKT * 136) : (128 * 20);
    constexpr int BST = 72;
    constexpr int BSZ = BKT * 72;
    constexpr int STG = ASZ + BSZ;

    const int tid  = threadIdx.x;
    const int wid  = tid >> 5, lane = tid & 31;
    const int grp  = lane >> 2, tg = lane & 3;
    const int wm   = (wid >> 1) * 64;   // 2 warps in m
    const int wn   = (wid & 1) * 32;    // 2 warps in n
    const int bm   = blockIdx.y * 128;
    const int bn   = blockIdx.x * 64;

    float acc[4][4][4];
#pragma unroll
    for (int i = 0; i < 4; i++)
#pragma unroll
        for (int j = 0; j < 4; j++)
#pragma unroll
            for (int k = 0; k < 4; k++) acc[i][j][k] = 0.0f;

    auto load_stage = [&](int kt, int s) {
        float* As = sm + s * STG;
        float* Bs = As + ASZ;
        const int k0 = kt * BKT;
        if (!TRANSA) {
            // A tile: 128 rows (m) x 16 (k); smem [m][20]
#pragma unroll
            for (int h = 0; h < 4; h++) {
                int ch = tid + h * 128;          // 0..511
                int r = ch >> 2, c = ch & 3;
                cpasync16(smem_u32(As + r * AST + c * 4),
                          A + (size_t)(bm + r) * 4096 + k0 + c * 4);
            }
        } else {
            // A tile: 16 rows (k) x 128 (m); smem [k][136]
#pragma unroll
            for (int h = 0; h < 4; h++) {
                int ch = tid + h * 128;
                int r = ch >> 5, c = ch & 31;
                cpasync16(smem_u32(As + r * AST + c * 4),
                          A + (size_t)(k0 + r) * 4096 + bm + c * 4);
            }
        }
        // B tile: 16 rows (k) x 64 (n); smem [k][72]
#pragma unroll
        for (int h = 0; h < 2; h++) {
            int ch = tid + h * 128;              // 0..255
            int r = ch >> 4, c = ch & 15;
            cpasync16(smem_u32(Bs + r * BST + c * 4),
                      B + (size_t)(k0 + r) * (size_t)ncols + bn + c * 4);
        }
        asm volatile("cp.async.commit_group;" ::: "memory");
    };

    const int NT = 4096 / BKT;  // 256 k-tiles

    for (int kt = 0; kt < STAGES - 1; kt++) load_stage(kt, kt);

    for (int kt = 0; kt < NT; kt++) {
        asm volatile("cp.async.wait_group %0;" :: "n"(STAGES - 2) : "memory");
        __syncthreads();

        int nx = kt + STAGES - 1;
        if (nx < NT) load_stage(nx, nx % STAGES);

        const float* As = sm + (kt % STAGES) * STG;
        const float* Bs = As + ASZ;

#pragma unroll
        for (int kk = 0; kk < BKT; kk += 8) {
            uint32_t af[4][4], bf[4][2];
#pragma unroll
            for (int mf = 0; mf < 4; mf++) {
                if (!TRANSA) {
                    const float* p = As + (wm + mf * 16 + grp) * AST + kk + tg;
                    af[mf][0] = __float_as_uint(p[0]);
                    af[mf][1] = __float_as_uint(p[8 * AST]);
                    af[mf][2] = __float_as_uint(p[4]);
                    af[mf][3] = __float_as_uint(p[8 * AST + 4]);
                } else {
                    const float* p = As + (kk + tg) * AST + wm + mf * 16 + grp;
                    af[mf][0] = __float_as_uint(p[0]);
                    af[mf][1] = __float_as_uint(p[8]);
                    af[mf][2] = __float_as_uint(p[4 * AST]);
                    af[mf][3] = __float_as_uint(p[4 * AST + 8]);
                }
            }
#pragma unroll
            for (int nf = 0; nf < 4; nf++) {
                const float* p = Bs + (kk + tg) * BST + wn + nf * 8 + grp;
                bf[nf][0] = __float_as_uint(p[0]);
                bf[nf][1] = __float_as_uint(p[4 * BST]);
            }
#pragma unroll
            for (int mf = 0; mf < 4; mf++)
#pragma unroll
                for (int nf = 0; nf < 4; nf++)
                    mma_tf32(acc[mf][nf], af[mf], bf[nf]);
        }
    }

    // epilogue
#pragma unroll
    for (int mf = 0; mf < 4; mf++)
#pragma unroll
        for (int nf = 0; nf < 4; nf++) {
            int row = bm + wm + mf * 16 + grp;
            int col = bn + wn + nf * 8 + 2 * tg;
            float2 v0 = make_float2(acc[mf][nf][0], acc[mf][nf][1]);
            float2 v1 = make_float2(acc[mf][nf][2], acc[mf][nf][3]);
            *reinterpret_cast<float2*>(C + (size_t)row * ncols + col) = v0;
            *reinterpret_cast<float2*>(C + (size_t)(row + 8) * ncols + col) = v1;
        }
}

// ---------------- K -> tf32 rounding pass --------------------------------------
__global__ void __launch_bounds__(256) kround_kernel(const float4* __restrict__ K,
                                                     float4* __restrict__ O) {
    size_t i = (size_t)blockIdx.x * 256 + threadIdx.x;   // 4M float4
    float4 v = K[i];
    v.x = tf32r(v.x); v.y = tf32r(v.y); v.z = tf32r(v.z); v.w = tf32r(v.w);
    O[i] = v;
}

// ---------------- prep: tf32-rounded f and f*flog from U -----------------------
__global__ void __launch_bounds__(512) prep_kernel(const float* __restrict__ U) {
    int i = blockIdx.x, j = threadIdx.x;
    float u    = U[i * BDIM + j];
    float flog = LAMDA * logf(LAMDA / (LAMDA - u));
    float f    = expf(flog);
    g_B2[(size_t)i * B2R + j]        = tf32r(f);
    g_B2[(size_t)i * B2R + BDIM + j] = tf32r(f * flog);
}

// ---------------- reductions ---------------------------------------------------
__device__ __forceinline__ float warp_sum(float v) {
#pragma unroll
    for (int o = 16; o > 0; o >>= 1) v += __shfl_down_sync(0xffffffffu, v, o);
    return v;
}

// ---------------- epilogue 1: a, S1, S2, S3 ------------------------------------
__global__ void __launch_bounds__(512) epi1_kernel(const float* __restrict__ P) {
    __shared__ float sh1[16], sh2[16], sh3[16];
    int i = blockIdx.x, j = threadIdx.x;
    float kf = g_C[(size_t)i * B2R + j];
    float g  = g_C[(size_t)i * B2R + BDIM + j];
    float p  = P[(size_t)i * BDIM + j];
    float a  = p / kf;
    g_a[(size_t)i * BDIM + j] = tf32r(a);

    float s1 = a * g;
    float s2 = p * (logf(p) - logf(kf));
    float s3 = p;

    s1 = warp_sum(s1); s2 = warp_sum(s2); s3 = warp_sum(s3);
    int lane = j & 31, w = j >> 5;
    if (lane == 0) { sh1[w] = s1; sh2[w] = s2; sh3[w] = s3; }
    __syncthreads();
    if (w == 0) {
        float v1 = (lane < 16) ? sh1[lane] : 0.0f;
        float v2 = (lane < 16) ? sh2[lane] : 0.0f;
        float v3 = (lane < 16) ? sh3[lane] : 0.0f;
        v1 = warp_sum(v1); v2 = warp_sum(v2); v3 = warp_sum(v3);
        if (lane == 0) { g_p1[i] = v1; g_p2[i] = v2; g_p3[i] = v3; }
    }
}

// ---------------- epilogue 2: S4 = sum f*(K^T a)*(eps*flog + lamda) ------------
__global__ void __launch_bounds__(512) epi2_kernel(const float* __restrict__ U) {
    __shared__ float sh[16];
    int i = blockIdx.x, j = threadIdx.x;
    float kta  = g_KTa[(size_t)i * BDIM + j];
    float u    = U[(size_t)i * BDIM + j];
    float flog = LAMDA * logf(LAMDA / (LAMDA - u));
    float f    = expf(flog);
    float s4   = f * kta * (EPSV * flog + LAMDA);

    s4 = warp_sum(s4);
    int lane = j & 31, w = j >> 5;
    if (lane == 0) sh[w] = s4;
    __syncthreads();
    if (w == 0) {
        float v = (lane < 16) ? sh[lane] : 0.0f;
        v = warp_sum(v);
        if (lane == 0) g_p4[i] = v;
    }
}

// ---------------- final combine ------------------------------------------------
__global__ void __launch_bounds__(1024) final_kernel(float* __restrict__ out) {
    __shared__ float sh1[32], sh2[32], sh3[32], sh4[32];
    int t = threadIdx.x;
    float s1 = 0, s2 = 0, s3 = 0, s4 = 0;
    for (int i = t; i < NDIM; i += 1024) {
        s1 += g_p1[i]; s2 += g_p2[i]; s3 += g_p3[i]; s4 += g_p4[i];
    }
    s1 = warp_sum(s1); s2 = warp_sum(s2); s3 = warp_sum(s3); s4 = warp_sum(s4);
    int lane = t & 31, w = t >> 5;
    if (lane == 0) { sh1[w] = s1; sh2[w] = s2; sh3[w] = s3; sh4[w] = s4; }
    __syncthreads();
    if (w == 0) {
        float v1 = sh1[lane], v2 = sh2[lane], v3 = sh3[lane], v4 = sh4[lane];
        v1 = warp_sum(v1); v2 = warp_sum(v2); v3 = warp_sum(v3); v4 = warp_sum(v4);
        if (lane == 0) out[0] = EPSV * (v1 + v2 - v3) - v4;
    }
}

// ---------------- launch -------------------------------------------------------
extern "C" void kernel_launch(void* const* d_in, const int* in_sizes, int n_in,
                              void* d_out, int out_size) {
    const float* U = (const float*)d_in[0];
    const float* P = (const float*)d_in[1];
    const float* K = (const float*)d_in[2];
    float* out = (float*)d_out;

    float *pK32, *pB2, *pC, *pa, *pKTa;
    cudaGetSymbolAddress((void**)&pK32, g_K32);
    cudaGetSymbolAddress((void**)&pB2,  g_B2);
    cudaGetSymbolAddress((void**)&pC,   g_C);
    cudaGetSymbolAddress((void**)&pa,   g_a);
    cudaGetSymbolAddress((void**)&pKTa, g_KTa);

    constexpr int SMEM_F = STAGES * (128 * 20 + BKT * 72) * 4;   // 44544 B
    constexpr int SMEM_T = STAGES * (BKT * 136 + BKT * 72) * 4;  // 39936 B
    cudaFuncSetAttribute(gemm_mma<false>,
                         cudaFuncAttributeMaxDynamicSharedMemorySize, SMEM_F);
    cudaFuncSetAttribute(gemm_mma<true>,
                         cudaFuncAttributeMaxDynamicSharedMemorySize, SMEM_T);

    // 1) pre-round K to tf32 bits; f, f*flog (rounded)
    kround_kernel<<<(NDIM * NDIM / 4) / 256, 256>>>((const float4*)K, (float4*)pK32);
    prep_kernel<<<NDIM, 512>>>(U);
    // 2) [Kf | K@(f*flog)] = K @ [f | f*flog]
    gemm_mma<false><<<dim3(B2R / 64, NDIM / 128), 128, SMEM_F>>>(pK32, pB2, pC, B2R);
    // 3) a = P/Kf + partials
    epi1_kernel<<<NDIM, 512>>>(P);
    // 4) K^T @ a
    gemm_mma<true><<<dim3(BDIM / 64, NDIM / 128), 128, SMEM_T>>>(pK32, pa, pKTa, BDIM);
    // 5) S4 partials
    epi2_kernel<<<NDIM, 512>>>(U);
    // 6) combine
    final_kernel<<<1, 1024>>>(out);
}

// round 8
// speedup vs baseline: 1.0279x; 1.0279x over previous
#include <cuda_runtime.h>
#include <math.h>
#include <stdint.h>

#define NDIM  4096
#define BDIM  512
#define B2R   1024
#define EPSV  1.0f
#define LAMDA 10.0f

// ---------------- scratch (static device globals; no allocation) -------------
__device__ float g_K32[NDIM * NDIM];   // K pre-rounded to tf32 bit patterns (64MB)
__device__ float g_B2 [NDIM * B2R ];   // [4096][1024]: cols 0..511 = f, 512..1023 = f*flog (tf32)
__device__ float g_C  [NDIM * B2R ];   // [4096][1024]: cols 0..511 = Kf, 512..1023 = K@(f*flog)
__device__ float g_a  [NDIM * BDIM];   // a = P / Kf (tf32-rounded)  [4096][512]
__device__ float g_KTa[NDIM * BDIM];   // K^T @ a      [4096][512]
__device__ float g_p1[NDIM], g_p2[NDIM], g_p3[NDIM], g_p4[NDIM];

// ---------------- helpers -----------------------------------------------------
__device__ __forceinline__ uint32_t smem_u32(const void* p) {
    return (uint32_t)__cvta_generic_to_shared(p);
}
__device__ __forceinline__ void cpasync16(uint32_t dst, const void* src) {
    asm volatile("cp.async.cg.shared.global [%0], [%1], 16;"
                 :: "r"(dst), "l"(src) : "memory");
}
__device__ __forceinline__ float tf32r(float x) {
    uint32_t r;
    asm("cvt.rna.tf32.f32 %0, %1;" : "=r"(r) : "f"(x));
    return __uint_as_float(r);
}
__device__ __forceinline__ void mma_tf32(float* c, const uint32_t* a, const uint32_t* b) {
    asm volatile(
        "mma.sync.aligned.m16n8k8.row.col.f32.tf32.tf32.f32 "
        "{%0,%1,%2,%3}, {%4,%5,%6,%7}, {%8,%9}, {%0,%1,%2,%3};"
        : "+f"(c[0]), "+f"(c[1]), "+f"(c[2]), "+f"(c[3])
        : "r"(a[0]), "r"(a[1]), "r"(a[2]), "r"(a[3]), "r"(b[0]), "r"(b[1]));
}

// ---------------- tensor-core tf32 GEMM with split-K ---------------------------
// C[4096, ncols] += op(K32)[4096,4096] @ B[4096, ncols] over this split's k-range.
// BM=BN=128, 256 threads (2x4 warps, warp tile 64x32), 3-stage cp.async.
// blockIdx.z selects a k-chunk of `ktiles` BKT-tiles; results atomicAdd'ed to C.
#define STAGES 3
#define BKT 16

template <bool TRANSA>
__global__ void __launch_bounds__(256, 2)
gemm_mma(const float* __restrict__ A, const float* __restrict__ B,
         float* __restrict__ C, int ncols, int ktiles)
{
    extern __shared__ float sm[];
    constexpr int AST = TRANSA ? 136 : 20;
    constexpr int ASZ = TRANSA ? (BKT * 136) : (128 * 20);
    constexpr int BST = 136;
    constexpr int BSZ = BKT * 136;
    constexpr int STG = ASZ + BSZ;

    const int tid  = threadIdx.x;
    const int wid  = tid >> 5, lane = tid & 31;
    const int grp  = lane >> 2, tg = lane & 3;
    const int wm   = (wid >> 2) * 64;   // 2 warps in m
    const int wn   = (wid & 3) * 32;    // 4 warps in n
    const int bm   = blockIdx.y * 128;
    const int bn   = blockIdx.x * 128;
    const int kt0  = blockIdx.z * ktiles;

    float acc[4][4][4];
#pragma unroll
    for (int i = 0; i < 4; i++)
#pragma unroll
        for (int j = 0; j < 4; j++)
#pragma unroll
            for (int k = 0; k < 4; k++) acc[i][j][k] = 0.0f;

    auto load_stage = [&](int kt, int s) {
        float* As = sm + s * STG;
        float* Bs = As + ASZ;
        const int k0 = (kt0 + kt) * BKT;
        if (!TRANSA) {
            // A tile: 128 rows (m) x 16 (k); smem [m][20]
#pragma unroll
            for (int h = 0; h < 2; h++) {
                int ch = tid + h * 256;          // 0..511
                int r = ch >> 2, c = ch & 3;
                cpasync16(smem_u32(As + r * AST + c * 4),
                          A + (size_t)(bm + r) * 4096 + k0 + c * 4);
            }
        } else {
            // A tile: 16 rows (k) x 128 (m); smem [k][136]
#pragma unroll
            for (int h = 0; h < 2; h++) {
                int ch = tid + h * 256;
                int r = ch >> 5, c = ch & 31;
                cpasync16(smem_u32(As + r * AST + c * 4),
                          A + (size_t)(k0 + r) * 4096 + bm + c * 4);
            }
        }
        // B tile: 16 rows (k) x 128 (n); smem [k][136]
#pragma unroll
        for (int h = 0; h < 2; h++) {
            int ch = tid + h * 256;
            int r = ch >> 5, c = ch & 31;
            cpasync16(smem_u32(Bs + r * BST + c * 4),
                      B + (size_t)(k0 + r) * (size_t)ncols + bn + c * 4);
        }
        asm volatile("cp.async.commit_group;" ::: "memory");
    };

    for (int kt = 0; kt < STAGES - 1; kt++) load_stage(kt, kt);

    for (int kt = 0; kt < ktiles; kt++) {
        asm volatile("cp.async.wait_group %0;" :: "n"(STAGES - 2) : "memory");
        __syncthreads();

        int nx = kt + STAGES - 1;
        if (nx < ktiles) load_stage(nx, nx % STAGES);

        const float* As = sm + (kt % STAGES) * STG;
        const float* Bs = As + ASZ;

#pragma unroll
        for (int kk = 0; kk < BKT; kk += 8) {
            uint32_t af[4][4], bf[4][2];
#pragma unroll
            for (int mf = 0; mf < 4; mf++) {
                if (!TRANSA) {
                    const float* p = As + (wm + mf * 16 + grp) * AST + kk + tg;
                    af[mf][0] = __float_as_uint(p[0]);
                    af[mf][1] = __float_as_uint(p[8 * AST]);
                    af[mf][2] = __float_as_uint(p[4]);
                    af[mf][3] = __float_as_uint(p[8 * AST + 4]);
                } else {
                    const float* p = As + (kk + tg) * AST + wm + mf * 16 + grp;
                    af[mf][0] = __float_as_uint(p[0]);
                    af[mf][1] = __float_as_uint(p[8]);
                    af[mf][2] = __float_as_uint(p[4 * AST]);
                    af[mf][3] = __float_as_uint(p[4 * AST + 8]);
                }
            }
#pragma unroll
            for (int nf = 0; nf < 4; nf++) {
                const float* p = Bs + (kk + tg) * BST + wn + nf * 8 + grp;
                bf[nf][0] = __float_as_uint(p[0]);
                bf[nf][1] = __float_as_uint(p[4 * BST]);
            }
#pragma unroll
            for (int mf = 0; mf < 4; mf++)
#pragma unroll
                for (int nf = 0; nf < 4; nf++)
                    mma_tf32(acc[mf][nf], af[mf], bf[nf]);
        }
    }

    // epilogue: accumulate this split's partial into C
#pragma unroll
    for (int mf = 0; mf < 4; mf++)
#pragma unroll
        for (int nf = 0; nf < 4; nf++) {
            int row = bm + wm + mf * 16 + grp;
            int col = bn + wn + nf * 8 + 2 * tg;
            float* c0 = C + (size_t)row * ncols + col;
            float* c1 = C + (size_t)(row + 8) * ncols + col;
            atomicAdd(c0,     acc[mf][nf][0]);
            atomicAdd(c0 + 1, acc[mf][nf][1]);
            atomicAdd(c1,     acc[mf][nf][2]);
            atomicAdd(c1 + 1, acc[mf][nf][3]);
        }
}

// ---------------- K -> tf32 rounding pass --------------------------------------
__global__ void __launch_bounds__(256) kround_kernel(const float4* __restrict__ K,
                                                     float4* __restrict__ O) {
    size_t i = (size_t)blockIdx.x * 256 + threadIdx.x;   // 4M float4
    float4 v = K[i];
    v.x = tf32r(v.x); v.y = tf32r(v.y); v.z = tf32r(v.z); v.w = tf32r(v.w);
    O[i] = v;
}

// ---------------- prep: tf32-rounded f and f*flog from U -----------------------
__global__ void __launch_bounds__(512) prep_kernel(const float* __restrict__ U) {
    int i = blockIdx.x, j = threadIdx.x;
    float u    = U[i * BDIM + j];
    float flog = LAMDA * logf(LAMDA / (LAMDA - u));
    float f    = expf(flog);
    g_B2[(size_t)i * B2R + j]        = tf32r(f);
    g_B2[(size_t)i * B2R + BDIM + j] = tf32r(f * flog);
}

// ---------------- reductions ---------------------------------------------------
__device__ __forceinline__ float warp_sum(float v) {
#pragma unroll
    for (int o = 16; o > 0; o >>= 1) v += __shfl_down_sync(0xffffffffu, v, o);
    return v;
}

// ---------------- epilogue 1: a, S1, S2, S3 ------------------------------------
__global__ void __launch_bounds__(512) epi1_kernel(const float* __restrict__ P) {
    __shared__ float sh1[16], sh2[16], sh3[16];
    int i = blockIdx.x, j = threadIdx.x;
    float kf = g_C[(size_t)i * B2R + j];
    float g  = g_C[(size_t)i * B2R + BDIM + j];
    float p  = P[(size_t)i * BDIM + j];
    float a  = p / kf;
    g_a[(size_t)i * BDIM + j] = tf32r(a);

    float s1 = a * g;
    float s2 = p * (logf(p) - logf(kf));
    float s3 = p;

    s1 = warp_sum(s1); s2 = warp_sum(s2); s3 = warp_sum(s3);
    int lane = j & 31, w = j >> 5;
    if (lane == 0) { sh1[w] = s1; sh2[w] = s2; sh3[w] = s3; }
    __syncthreads();
    if (w == 0) {
        float v1 = (lane < 16) ? sh1[lane] : 0.0f;
        float v2 = (lane < 16) ? sh2[lane] : 0.0f;
        float v3 = (lane < 16) ? sh3[lane] : 0.0f;
        v1 = warp_sum(v1); v2 = warp_sum(v2); v3 = warp_sum(v3);
        if (lane == 0) { g_p1[i] = v1; g_p2[i] = v2; g_p3[i] = v3; }
    }
}

// ---------------- epilogue 2: S4 = sum f*(K^T a)*(eps*flog + lamda) ------------
__global__ void __launch_bounds__(512) epi2_kernel(const float* __restrict__ U) {
    __shared__ float sh[16];
    int i = blockIdx.x, j = threadIdx.x;
    float kta  = g_KTa[(size_t)i * BDIM + j];
    float u    = U[(size_t)i * BDIM + j];
    float flog = LAMDA * logf(LAMDA / (LAMDA - u));
    float f    = expf(flog);
    float s4   = f * kta * (EPSV * flog + LAMDA);

    s4 = warp_sum(s4);
    int lane = j & 31, w = j >> 5;
    if (lane == 0) sh[w] = s4;
    __syncthreads();
    if (w == 0) {
        float v = (lane < 16) ? sh[lane] : 0.0f;
        v = warp_sum(v);
        if (lane == 0) g_p4[i] = v;
    }
}

// ---------------- final combine ------------------------------------------------
__global__ void __launch_bounds__(1024) final_kernel(float* __restrict__ out) {
    __shared__ float sh1[32], sh2[32], sh3[32], sh4[32];
    int t = threadIdx.x;
    float s1 = 0, s2 = 0, s3 = 0, s4 = 0;
    for (int i = t; i < NDIM; i += 1024) {
        s1 += g_p1[i]; s2 += g_p2[i]; s3 += g_p3[i]; s4 += g_p4[i];
    }
    s1 = warp_sum(s1); s2 = warp_sum(s2); s3 = warp_sum(s3); s4 = warp_sum(s4);
    int lane = t & 31, w = t >> 5;
    if (lane == 0) { sh1[w] = s1; sh2[w] = s2; sh3[w] = s3; sh4[w] = s4; }
    __syncthreads();
    if (w == 0) {
        float v1 = sh1[lane], v2 = sh2[lane], v3 = sh3[lane], v4 = sh4[lane];
        v1 = warp_sum(v1); v2 = warp_sum(v2); v3 = warp_sum(v3); v4 = warp_sum(v4);
        if (lane == 0) out[0] = EPSV * (v1 + v2 - v3) - v4;
    }
}

// ---------------- launch -------------------------------------------------------
extern "C" void kernel_launch(void* const* d_in, const int* in_sizes, int n_in,
                              void* d_out, int out_size) {
    const float* U = (const float*)d_in[0];
    const float* P = (const float*)d_in[1];
    const float* K = (const float*)d_in[2];
    float* out = (float*)d_out;

    float *pK32, *pB2, *pC, *pa, *pKTa;
    cudaGetSymbolAddress((void**)&pK32, g_K32);
    cudaGetSymbolAddress((void**)&pB2,  g_B2);
    cudaGetSymbolAddress((void**)&pC,   g_C);
    cudaGetSymbolAddress((void**)&pa,   g_a);
    cudaGetSymbolAddress((void**)&pKTa, g_KTa);

    constexpr int SMEM_F = STAGES * (128 * 20 + BKT * 136) * 4;  // 56832 B
    constexpr int SMEM_T = STAGES * (BKT * 136 * 2) * 4;         // 52224 B
    cudaFuncSetAttribute(gemm_mma<false>,
                         cudaFuncAttributeMaxDynamicSharedMemorySize, SMEM_F);
    cudaFuncSetAttribute(gemm_mma<true>,
                         cudaFuncAttributeMaxDynamicSharedMemorySize, SMEM_T);
    cudaFuncSetAttribute(gemm_mma<false>,
                         cudaFuncAttributePreferredSharedMemoryCarveout, 100);
    cudaFuncSetAttribute(gemm_mma<true>,
                         cudaFuncAttributePreferredSharedMemoryCarveout, 100);

    // 0) zero split-K accumulators (graph-capturable async memset)
    cudaMemsetAsync(pC,   0, (size_t)NDIM * B2R  * sizeof(float), 0);
    cudaMemsetAsync(pKTa, 0, (size_t)NDIM * BDIM * sizeof(float), 0);

    // 1) pre-round K to tf32 bits; f, f*flog (rounded)
    kround_kernel<<<(NDIM * NDIM / 4) / 256, 256>>>((const float4*)K, (float4*)pK32);
    prep_kernel<<<NDIM, 512>>>(U);

    // 2) [Kf | K@(f*flog)] = K @ [f | f*flog]   (split-K = 2 -> 512 CTAs)
    gemm_mma<false><<<dim3(B2R / 128, NDIM / 128, 2), 256, SMEM_F>>>(
        pK32, pB2, pC, B2R, 4096 / BKT / 2);

    // 3) a = P/Kf + partials
    epi1_kernel<<<NDIM, 512>>>(P);

    // 4) K^T @ a   (split-K = 4 -> 512 CTAs)
    gemm_mma<true><<<dim3(BDIM / 128, NDIM / 128, 4), 256, SMEM_T>>>(
        pK32, pa, pKTa, BDIM, 4096 / BKT / 4);

    // 5) S4 partials
    epi2_kernel<<<NDIM, 512>>>(U);

    // 6) combine
    final_kernel<<<1, 1024>>>(out);
}

// round 10
// speedup vs baseline: 1.3578x; 1.3209x over previous
#include <cuda_runtime.h>
#include <cuda_bf16.h>
#include <math.h>
#include <stdint.h>

#define NDIM  4096
#define BDIM  512
#define B2R   1024
#define EPSV  1.0f
#define LAMDA 10.0f

// ---------------- scratch (static device globals; no allocation) -------------
__device__ __nv_bfloat16 g_Kb [NDIM * NDIM];   // K  bf16 [m][k]
__device__ __nv_bfloat16 g_KTb[NDIM * NDIM];   // K^T bf16 [m][k]
__device__ __nv_bfloat16 g_B2T[B2R  * NDIM];   // [f | f*flog]^T bf16 [n][k]
__device__ __nv_bfloat16 g_aTb[BDIM * NDIM];   // a^T bf16 [n][k]
__device__ float g_C  [NDIM * B2R ];           // [4096][1024]: Kf | K@(f*flog)
__device__ float g_KTa[NDIM * BDIM];           // K^T @ a [4096][512]
__device__ float g_r1[2048], g_r2[2048], g_r3[2048];
__device__ float g_p4[NDIM];

// ---------------- helpers -----------------------------------------------------
__device__ __forceinline__ uint32_t smem_u32(const void* p) {
    return (uint32_t)__cvta_generic_to_shared(p);
}
__device__ __forceinline__ void cpasync16(uint32_t dst, const void* src) {
    asm volatile("cp.async.cg.shared.global [%0], [%1], 16;"
                 :: "r"(dst), "l"(src) : "memory");
}
__device__ __forceinline__ void mma_bf16(float* c, const uint32_t* a, const uint32_t* b) {
    asm volatile(
        "mma.sync.aligned.m16n8k16.row.col.f32.bf16.bf16.f32 "
        "{%0,%1,%2,%3}, {%4,%5,%6,%7}, {%8,%9}, {%0,%1,%2,%3};"
        : "+f"(c[0]), "+f"(c[1]), "+f"(c[2]), "+f"(c[3])
        : "r"(a[0]), "r"(a[1]), "r"(a[2]), "r"(a[3]), "r"(b[0]), "r"(b[1]));
}

// ---------------- bf16 tensor-core GEMM: C += A @ B^T (split-K) ----------------
// A: [4096][4096] bf16 row-major (m x k).  B: [ncols][4096] bf16 row-major (n x k).
// C: [4096][ncols] f32, accumulated with atomicAdd.
// BM=BN=128, BKT=32, 256 threads (2x4 warps, warp tile 64x32), 3-stage cp.async.
#define STAGES 3
#define BKT 32
#define AST32 20                 // smem row stride in b32 units (40 bf16 = 80B)
#define TSZ32 (128 * AST32)     // one operand tile: 2560 b32 = 10240B
#define STG32 (2 * TSZ32)

__global__ void __launch_bounds__(256, 2)
gemm_bf16(const __nv_bfloat16* __restrict__ A, const __nv_bfloat16* __restrict__ B,
          float* __restrict__ C, int ncols, int ktiles)
{
    extern __shared__ uint32_t sm32[];

    const int tid  = threadIdx.x;
    const int wid  = tid >> 5, lane = tid & 31;
    const int grp  = lane >> 2, tg = lane & 3;
    const int wm   = (wid >> 2) * 64;   // 2 warps in m
    const int wn   = (wid & 3) * 32;    // 4 warps in n
    const int bm   = blockIdx.y * 128;
    const int bn   = blockIdx.x * 128;
    const int kt0  = blockIdx.z * ktiles;

    float acc[4][4][4];
#pragma unroll
    for (int i = 0; i < 4; i++)
#pragma unroll
        for (int j = 0; j < 4; j++)
#pragma unroll
            for (int k = 0; k < 4; k++) acc[i][j][k] = 0.0f;

    auto load_stage = [&](int kt, int s) {
        uint32_t* As = sm32 + s * STG32;
        uint32_t* Bs = As + TSZ32;
        const int k0 = (kt0 + kt) * BKT;
        // A tile: 128 rows x 32 bf16 (64B) -> 4 chunks of 16B per row
#pragma unroll
        for (int h = 0; h < 2; h++) {
            int ch = tid + h * 256;          // 0..511
            int r = ch >> 2, c = ch & 3;
            cpasync16(smem_u32(As + r * AST32 + c * 4),
                      A + (size_t)(bm + r) * 4096 + k0 + c * 8);
        }
        // B tile: 128 n-rows x 32 bf16
#pragma unroll
        for (int h = 0; h < 2; h++) {
            int ch = tid + h * 256;
            int r = ch >> 2, c = ch & 3;
            cpasync16(smem_u32(Bs + r * AST32 + c * 4),
                      B + (size_t)(bn + r) * 4096 + k0 + c * 8);
        }
        asm volatile("cp.async.commit_group;" ::: "memory");
    };

    for (int kt = 0; kt < STAGES - 1; kt++) load_stage(kt, kt);

    for (int kt = 0; kt < ktiles; kt++) {
        asm volatile("cp.async.wait_group %0;" :: "n"(STAGES - 2) : "memory");
        __syncthreads();

        int nx = kt + STAGES - 1;
        if (nx < ktiles) load_stage(nx, nx % STAGES);

        const uint32_t* As = sm32 + (kt % STAGES) * STG32;
        const uint32_t* Bs = As + TSZ32;

#pragma unroll
        for (int ks = 0; ks < 2; ks++) {           // two k=16 steps
            const int ktop = ks * 8;               // b32 offset
            uint32_t af[4][4], bf[4][2];
#pragma unroll
            for (int mf = 0; mf < 4; mf++) {
                const uint32_t* p = As + (wm + mf * 16 + grp) * AST32 + ktop + tg;
                af[mf][0] = p[0];
                af[mf][1] = p[8 * AST32];
                af[mf][2] = p[4];
                af[mf][3] = p[8 * AST32 + 4];
            }
#pragma unroll
            for (int nf = 0; nf < 4; nf++) {
                const uint32_t* p = Bs + (wn + nf * 8 + grp) * AST32 + ktop + tg;
                bf[nf][0] = p[0];
                bf[nf][1] = p[4];
            }
#pragma unroll
            for (int mf = 0; mf < 4; mf++)
#pragma unroll
                for (int nf = 0; nf < 4; nf++)
                    mma_bf16(acc[mf][nf], af[mf], bf[nf]);
        }
        __syncthreads();
    }

    // epilogue: accumulate this split's partial into C
#pragma unroll
    for (int mf = 0; mf < 4; mf++)
#pragma unroll
        for (int nf = 0; nf < 4; nf++) {
            int row = bm + wm + mf * 16 + grp;
            int col = bn + wn + nf * 8 + 2 * tg;
            float* c0 = C + (size_t)row * ncols + col;
            float* c1 = C + (size_t)(row + 8) * ncols + col;
            atomicAdd(c0,     acc[mf][nf][0]);
            atomicAdd(c0 + 1, acc[mf][nf][1]);
            atomicAdd(c1,     acc[mf][nf][2]);
            atomicAdd(c1 + 1, acc[mf][nf][3]);
        }
}

// ---------------- kprep: K -> bf16 (direct + transposed) -----------------------
__global__ void __launch_bounds__(1024) kprep_kernel(const float* __restrict__ K) {
    __shared__ float s[32][33];
    int tx = threadIdx.x, ty = threadIdx.y;
    int r0 = blockIdx.y * 32, c0 = blockIdx.x * 32;
    float v = K[(size_t)(r0 + ty) * NDIM + c0 + tx];
    g_Kb[(size_t)(r0 + ty) * NDIM + c0 + tx] = __float2bfloat16(v);
    s[ty][tx] = v;
    __syncthreads();
    g_KTb[(size_t)(c0 + ty) * NDIM + r0 + tx] = __float2bfloat16(s[tx][ty]);
}

// ---------------- prep: [f | f*flog]^T bf16 from U -----------------------------
__global__ void __launch_bounds__(1024) prep_kernel(const float* __restrict__ U) {
    __shared__ float fs[32][33], gs[32][33];
    int tx = threadIdx.x, ty = threadIdx.y;
    int i0 = blockIdx.x * 32, j0 = blockIdx.y * 32;
    float u    = U[(size_t)(i0 + ty) * BDIM + j0 + tx];
    float flog = LAMDA * logf(LAMDA / (LAMDA - u));
    float f    = expf(flog);
    fs[ty][tx] = f;
    gs[ty][tx] = f * flog;
    __syncthreads();
    g_B2T[(size_t)(j0 + ty)       * NDIM + i0 + tx] = __float2bfloat16(fs[tx][ty]);
    g_B2T[(size_t)(512 + j0 + ty) * NDIM + i0 + tx] = __float2bfloat16(gs[tx][ty]);
}

// ---------------- reductions ---------------------------------------------------
__device__ __forceinline__ float warp_sum(float v) {
#pragma unroll
    for (int o = 16; o > 0; o >>= 1) v += __shfl_down_sync(0xffffffffu, v, o);
    return v;
}

// ---------------- epilogue 1: a^T bf16, block partials S1,S2,S3 ----------------
__global__ void __launch_bounds__(1024) epi1_kernel(const float* __restrict__ P) {
    __shared__ float as[32][33];
    __shared__ float sh1[32], sh2[32], sh3[32];
    int tx = threadIdx.x, ty = threadIdx.y;
    int j0 = blockIdx.x * 32, i0 = blockIdx.y * 32;
    int i = i0 + ty, j = j0 + tx;

    float kf = g_C[(size_t)i * B2R + j];
    float g  = g_C[(size_t)i * B2R + 512 + j];
    float p  = P[(size_t)i * BDIM + j];
    float a  = p / kf;
    as[ty][tx] = a;

    float s1 = a * g;
    float s2 = p * (logf(p) - logf(kf));
    float s3 = p;

    int lt = ty * 32 + tx, lane = lt & 31, w = lt >> 5;
    s1 = warp_sum(s1); s2 = warp_sum(s2); s3 = warp_sum(s3);
    if (lane == 0) { sh1[w] = s1; sh2[w] = s2; sh3[w] = s3; }
    __syncthreads();

    g_aTb[(size_t)(j0 + ty) * NDIM + i0 + tx] = __float2bfloat16(as[tx][ty]);

    if (w == 0) {
        float v1 = sh1[lane], v2 = sh2[lane], v3 = sh3[lane];
        v1 = warp_sum(v1); v2 = warp_sum(v2); v3 = warp_sum(v3);
        if (lane == 0) {
            int bid = blockIdx.y * 16 + blockIdx.x;
            g_r1[bid] = v1; g_r2[bid] = v2; g_r3[bid] = v3;
        }
    }
}

// ---------------- epilogue 2: S4 = sum f*(K^T a)*(eps*flog + lamda) ------------
__global__ void __launch_bounds__(512) epi2_kernel(const float* __restrict__ U) {
    __shared__ float sh[16];
    int i = blockIdx.x, j = threadIdx.x;
    float kta  = g_KTa[(size_t)i * BDIM + j];
    float u    = U[(size_t)i * BDIM + j];
    float flog = LAMDA * logf(LAMDA / (LAMDA - u));
    float f    = expf(flog);
    float s4   = f * kta * (EPSV * flog + LAMDA);

    s4 = warp_sum(s4);
    int lane = j & 31, w = j >> 5;
    if (lane == 0) sh[w] = s4;
    __syncthreads();
    if (w == 0) {
        float v = (lane < 16) ? sh[lane] : 0.0f;
        v = warp_sum(v);
        if (lane == 0) g_p4[i] = v;
    }
}

// ---------------- final combine ------------------------------------------------
__global__ void __launch_bounds__(1024) final_kernel(float* __restrict__ out) {
    __shared__ float sh1[32], sh2[32], sh3[32], sh4[32];
    int t = threadIdx.x;
    float s1 = 0, s2 = 0, s3 = 0, s4 = 0;
    for (int i = t; i < 2048; i += 1024) { s1 += g_r1[i]; s2 += g_r2[i]; s3 += g_r3[i]; }
    for (int i = t; i < NDIM; i += 1024) s4 += g_p4[i];
    s1 = warp_sum(s1); s2 = warp_sum(s2); s3 = warp_sum(s3); s4 = warp_sum(s4);
    int lane = t & 31, w = t >> 5;
    if (lane == 0) { sh1[w] = s1; sh2[w] = s2; sh3[w] = s3; sh4[w] = s4; }
    __syncthreads();
    if (w == 0) {
        float v1 = sh1[lane], v2 = sh2[lane], v3 = sh3[lane], v4 = sh4[lane];
        v1 = warp_sum(v1); v2 = warp_sum(v2); v3 = warp_sum(v3); v4 = warp_sum(v4);
        if (lane == 0) out[0] = EPSV * (v1 + v2 - v3) - v4;
    }
}

// ---------------- launch -------------------------------------------------------
extern "C" void kernel_launch(void* const* d_in, const int* in_sizes, int n_in,
                              void* d_out, int out_size) {
    const float* U = (const float*)d_in[0];
    const float* P = (const float*)d_in[1];
    const float* K = (const float*)d_in[2];
    float* out = (float*)d_out;

    __nv_bfloat16 *pKb, *pKTb, *pB2T, *paTb;
    float *pC, *pKTa;
    cudaGetSymbolAddress((void**)&pKb,  g_Kb);
    cudaGetSymbolAddress((void**)&pKTb, g_KTb);
    cudaGetSymbolAddress((void**)&pB2T, g_B2T);
    cudaGetSymbolAddress((void**)&paTb, g_aTb);
    cudaGetSymbolAddress((void**)&pC,   g_C);
    cudaGetSymbolAddress((void**)&pKTa, g_KTa);

    constexpr int SMEM_B = STAGES * STG32 * 4;   // 61440 B
    cudaFuncSetAttribute(gemm_bf16,
                         cudaFuncAttributeMaxDynamicSharedMemorySize, SMEM_B);
    cudaFuncSetAttribute(gemm_bf16,
                         cudaFuncAttributePreferredSharedMemoryCarveout, 100);

    dim3 t32(32, 32);

    // 0) zero split-K accumulators
    cudaMemsetAsync(pC,   0, (size_t)NDIM * B2R  * sizeof(float), 0);
    cudaMemsetAsync(pKTa, 0, (size_t)NDIM * BDIM * sizeof(float), 0);

    // 1) K -> bf16 (both orientations); [f | f*flog]^T bf16
    kprep_kernel<<<dim3(NDIM / 32, NDIM / 32), t32>>>(K);
    prep_kernel<<<dim3(NDIM / 32, BDIM / 32), t32>>>(U);

    // 2) [Kf | K@(f*flog)] = Kb @ B2T^T    (split-K = 2 -> 512 CTAs)
    gemm_bf16<<<dim3(B2R / 128, NDIM / 128, 2), 256, SMEM_B>>>(
        pKb, pB2T, pC, B2R, 4096 / BKT / 2);

    // 3) a = P/Kf -> a^T bf16 + partials
    epi1_kernel<<<dim3(BDIM / 32, NDIM / 32), t32>>>(P);

    // 4) K^T @ a = KTb @ aTb^T             (split-K = 4 -> 512 CTAs)
    gemm_bf16<<<dim3(BDIM / 128, NDIM / 128, 4), 256, SMEM_B>>>(
        pKTb, paTb, pKTa, BDIM, 4096 / BKT / 4);

    // 5) S4 partials
    epi2_kernel<<<NDIM, 512>>>(U);

    // 6) combine
    final_kernel<<<1, 1024>>>(out);
}

// round 11
// speedup vs baseline: 1.4768x; 1.0877x over previous
#include <cuda_runtime.h>
#include <cuda_bf16.h>
#include <math.h>
#include <stdint.h>

#define NDIM  4096
#define BDIM  512
#define B2R   1024
#define EPSV  1.0f
#define LAMDA 10.0f

// ---------------- scratch (static device globals; no allocation) -------------
__device__ __nv_bfloat16 g_Kb [NDIM * NDIM];   // K  bf16 [m][k]
__device__ __nv_bfloat16 g_KTb[NDIM * NDIM];   // K^T bf16 [m][k]
__device__ __nv_bfloat16 g_B2T[B2R  * NDIM];   // [f | f*flog]^T bf16 [n][k]
__device__ __nv_bfloat16 g_aTb[BDIM * NDIM];   // a^T bf16 [n][k]
__device__ float g_C  [NDIM * B2R ];           // [4096][1024]: Kf | K@(f*flog)
__device__ float g_KTa[NDIM * BDIM];           // K^T @ a [4096][512]
__device__ float g_r1[2048], g_r2[2048], g_r3[2048];
__device__ float g_p4[NDIM];

// ---------------- helpers -----------------------------------------------------
__device__ __forceinline__ uint32_t smem_u32(const void* p) {
    return (uint32_t)__cvta_generic_to_shared(p);
}
__device__ __forceinline__ void cpasync16(uint32_t dst, const void* src) {
    asm volatile("cp.async.cg.shared.global [%0], [%1], 16;"
                 :: "r"(dst), "l"(src) : "memory");
}
__device__ __forceinline__ void mma_bf16(float* c, const uint32_t* a, const uint32_t* b) {
    asm volatile(
        "mma.sync.aligned.m16n8k16.row.col.f32.bf16.bf16.f32 "
        "{%0,%1,%2,%3}, {%4,%5,%6,%7}, {%8,%9}, {%0,%1,%2,%3};"
        : "+f"(c[0]), "+f"(c[1]), "+f"(c[2]), "+f"(c[3])
        : "r"(a[0]), "r"(a[1]), "r"(a[2]), "r"(a[3]), "r"(b[0]), "r"(b[1]));
}
__device__ __forceinline__ void ldsm4(uint32_t& r0, uint32_t& r1, uint32_t& r2,
                                      uint32_t& r3, uint32_t addr) {
    asm volatile("ldmatrix.sync.aligned.m8n8.x4.shared.b16 {%0,%1,%2,%3}, [%4];"
                 : "=r"(r0), "=r"(r1), "=r"(r2), "=r"(r3) : "r"(addr));
}

// ---------------- bf16 tensor-core GEMM: C += A @ B^T (split-K) ----------------
// A: [4096][4096] bf16 row-major (m x k).  B: [ncols][4096] bf16 row-major (n x k).
// C: [4096][ncols] f32, accumulated with atomicAdd.
// BM=BN=128, BKT=32, 256 threads (2x4 warps, warp tile 64x32), 3-stage cp.async.
#define STAGES 3
#define BKT 32
#define AST32 20                 // smem row stride in b32 units (40 bf16 = 80B)
#define TSZ32 (128 * AST32)      // one operand tile: 2560 b32 = 10240B
#define STG32 (2 * TSZ32)

__global__ void __launch_bounds__(256, 2)
gemm_bf16(const __nv_bfloat16* __restrict__ A, const __nv_bfloat16* __restrict__ B,
          float* __restrict__ C, int ncols, int ktiles)
{
    extern __shared__ uint32_t sm32[];

    const int tid  = threadIdx.x;
    const int wid  = tid >> 5, lane = tid & 31;
    const int grp  = lane >> 2, tg = lane & 3;
    const int wm   = (wid >> 2) * 64;   // 2 warps in m
    const int wn   = (wid & 3) * 32;    // 4 warps in n
    const int bm   = blockIdx.y * 128;
    const int bn   = blockIdx.x * 128;
    const int kt0  = blockIdx.z * ktiles;

    // ldmatrix per-lane row selectors (constant across loop)
    const int a_row = (lane & 15);                       // + wm + mf*16
    const int a_kc  = (lane >> 4);                       // + ks*2
    const int b_row = (lane & 7) + ((lane >> 4) & 1) * 8; // + wn + np*16
    const int b_kc  = ((lane >> 3) & 1);                 // + ks*2

    float acc[4][4][4];
#pragma unroll
    for (int i = 0; i < 4; i++)
#pragma unroll
        for (int j = 0; j < 4; j++)
#pragma unroll
            for (int k = 0; k < 4; k++) acc[i][j][k] = 0.0f;

    auto load_stage = [&](int kt, int s) {
        uint32_t* As = sm32 + s * STG32;
        uint32_t* Bs = As + TSZ32;
        const int k0 = (kt0 + kt) * BKT;
#pragma unroll
        for (int h = 0; h < 2; h++) {
            int ch = tid + h * 256;          // 0..511
            int r = ch >> 2, c = ch & 3;
            cpasync16(smem_u32(As + r * AST32 + c * 4),
                      A + (size_t)(bm + r) * 4096 + k0 + c * 8);
        }
#pragma unroll
        for (int h = 0; h < 2; h++) {
            int ch = tid + h * 256;
            int r = ch >> 2, c = ch & 3;
            cpasync16(smem_u32(Bs + r * AST32 + c * 4),
                      B + (size_t)(bn + r) * 4096 + k0 + c * 8);
        }
        asm volatile("cp.async.commit_group;" ::: "memory");
    };

    for (int kt = 0; kt < STAGES - 1; kt++) load_stage(kt, kt);

    for (int kt = 0; kt < ktiles; kt++) {
        asm volatile("cp.async.wait_group %0;" :: "n"(STAGES - 2) : "memory");
        __syncthreads();

        int nx = kt + STAGES - 1;
        if (nx < ktiles) load_stage(nx, nx % STAGES);

        const uint32_t Asb = smem_u32(sm32 + (kt % STAGES) * STG32);
        const uint32_t Bsb = Asb + TSZ32 * 4;

#pragma unroll
        for (int ks = 0; ks < 2; ks++) {           // two k=16 steps
            uint32_t af[4][4], bf[4][2];
#pragma unroll
            for (int mf = 0; mf < 4; mf++) {
                uint32_t addr = Asb + (uint32_t)(wm + mf * 16 + a_row) * 80u
                              + (uint32_t)(ks * 2 + a_kc) * 16u;
                ldsm4(af[mf][0], af[mf][1], af[mf][2], af[mf][3], addr);
            }
#pragma unroll
            for (int np = 0; np < 2; np++) {
                uint32_t addr = Bsb + (uint32_t)(wn + np * 16 + b_row) * 80u
                              + (uint32_t)(ks * 2 + b_kc) * 16u;
                ldsm4(bf[2 * np][0], bf[2 * np][1],
                      bf[2 * np + 1][0], bf[2 * np + 1][1], addr);
            }
#pragma unroll
            for (int mf = 0; mf < 4; mf++)
#pragma unroll
                for (int nf = 0; nf < 4; nf++)
                    mma_bf16(acc[mf][nf], af[mf], bf[nf]);
        }
    }

    // epilogue: accumulate this split's partial into C
#pragma unroll
    for (int mf = 0; mf < 4; mf++)
#pragma unroll
        for (int nf = 0; nf < 4; nf++) {
            int row = bm + wm + mf * 16 + grp;
            int col = bn + wn + nf * 8 + 2 * tg;
            float* c0 = C + (size_t)row * ncols + col;
            float* c1 = C + (size_t)(row + 8) * ncols + col;
            atomicAdd(c0,     acc[mf][nf][0]);
            atomicAdd(c0 + 1, acc[mf][nf][1]);
            atomicAdd(c1,     acc[mf][nf][2]);
            atomicAdd(c1 + 1, acc[mf][nf][3]);
        }
}

// ---------------- kprep: K -> bf16 (direct + transposed) -----------------------
__global__ void __launch_bounds__(1024) kprep_kernel(const float* __restrict__ K) {
    __shared__ float s[32][33];
    int tx = threadIdx.x, ty = threadIdx.y;
    int r0 = blockIdx.y * 32, c0 = blockIdx.x * 32;
    float v = K[(size_t)(r0 + ty) * NDIM + c0 + tx];
    g_Kb[(size_t)(r0 + ty) * NDIM + c0 + tx] = __float2bfloat16(v);
    s[ty][tx] = v;
    __syncthreads();
    g_KTb[(size_t)(c0 + ty) * NDIM + r0 + tx] = __float2bfloat16(s[tx][ty]);
}

// ---------------- prep: [f | f*flog]^T bf16 from U -----------------------------
__global__ void __launch_bounds__(1024) prep_kernel(const float* __restrict__ U) {
    __shared__ float fs[32][33], gs[32][33];
    int tx = threadIdx.x, ty = threadIdx.y;
    int i0 = blockIdx.x * 32, j0 = blockIdx.y * 32;
    float u    = U[(size_t)(i0 + ty) * BDIM + j0 + tx];
    float flog = LAMDA * logf(LAMDA / (LAMDA - u));
    float f    = expf(flog);
    fs[ty][tx] = f;
    gs[ty][tx] = f * flog;
    __syncthreads();
    g_B2T[(size_t)(j0 + ty)       * NDIM + i0 + tx] = __float2bfloat16(fs[tx][ty]);
    g_B2T[(size_t)(512 + j0 + ty) * NDIM + i0 + tx] = __float2bfloat16(gs[tx][ty]);
}

// ---------------- reductions ---------------------------------------------------
__device__ __forceinline__ float warp_sum(float v) {
#pragma unroll
    for (int o = 16; o > 0; o >>= 1) v += __shfl_down_sync(0xffffffffu, v, o);
    return v;
}

// ---------------- epilogue 1: a^T bf16, block partials S1,S2,S3 ----------------
__global__ void __launch_bounds__(1024) epi1_kernel(const float* __restrict__ P) {
    __shared__ float as[32][33];
    __shared__ float sh1[32], sh2[32], sh3[32];
    int tx = threadIdx.x, ty = threadIdx.y;
    int j0 = blockIdx.x * 32, i0 = blockIdx.y * 32;
    int i = i0 + ty, j = j0 + tx;

    float kf = g_C[(size_t)i * B2R + j];
    float g  = g_C[(size_t)i * B2R + 512 + j];
    float p  = P[(size_t)i * BDIM + j];
    float a  = p / kf;
    as[ty][tx] = a;

    float s1 = a * g;
    float s2 = p * (logf(p) - logf(kf));
    float s3 = p;

    int lt = ty * 32 + tx, lane = lt & 31, w = lt >> 5;
    s1 = warp_sum(s1); s2 = warp_sum(s2); s3 = warp_sum(s3);
    if (lane == 0) { sh1[w] = s1; sh2[w] = s2; sh3[w] = s3; }
    __syncthreads();

    g_aTb[(size_t)(j0 + ty) * NDIM + i0 + tx] = __float2bfloat16(as[tx][ty]);

    if (w == 0) {
        float v1 = sh1[lane], v2 = sh2[lane], v3 = sh3[lane];
        v1 = warp_sum(v1); v2 = warp_sum(v2); v3 = warp_sum(v3);
        if (lane == 0) {
            int bid = blockIdx.y * 16 + blockIdx.x;
            g_r1[bid] = v1; g_r2[bid] = v2; g_r3[bid] = v3;
        }
    }
}

// ---------------- epilogue 2: S4 = sum f*(K^T a)*(eps*flog + lamda) ------------
__global__ void __launch_bounds__(512) epi2_kernel(const float* __restrict__ U) {
    __shared__ float sh[16];
    int i = blockIdx.x, j = threadIdx.x;
    float kta  = g_KTa[(size_t)i * BDIM + j];
    float u    = U[(size_t)i * BDIM + j];
    float flog = LAMDA * logf(LAMDA / (LAMDA - u));
    float f    = expf(flog);
    float s4   = f * kta * (EPSV * flog + LAMDA);

    s4 = warp_sum(s4);
    int lane = j & 31, w = j >> 5;
    if (lane == 0) sh[w] = s4;
    __syncthreads();
    if (w == 0) {
        float v = (lane < 16) ? sh[lane] : 0.0f;
        v = warp_sum(v);
        if (lane == 0) g_p4[i] = v;
    }
}

// ---------------- final combine ------------------------------------------------
__global__ void __launch_bounds__(1024) final_kernel(float* __restrict__ out) {
    __shared__ float sh1[32], sh2[32], sh3[32], sh4[32];
    int t = threadIdx.x;
    float s1 = 0, s2 = 0, s3 = 0, s4 = 0;
    for (int i = t; i < 2048; i += 1024) { s1 += g_r1[i]; s2 += g_r2[i]; s3 += g_r3[i]; }
    for (int i = t; i < NDIM; i += 1024) s4 += g_p4[i];
    s1 = warp_sum(s1); s2 = warp_sum(s2); s3 = warp_sum(s3); s4 = warp_sum(s4);
    int lane = t & 31, w = t >> 5;
    if (lane == 0) { sh1[w] = s1; sh2[w] = s2; sh3[w] = s3; sh4[w] = s4; }
    __syncthreads();
    if (w == 0) {
        float v1 = sh1[lane], v2 = sh2[lane], v3 = sh3[lane], v4 = sh4[lane];
        v1 = warp_sum(v1); v2 = warp_sum(v2); v3 = warp_sum(v3); v4 = warp_sum(v4);
        if (lane == 0) out[0] = EPSV * (v1 + v2 - v3) - v4;
    }
}

// ---------------- launch -------------------------------------------------------
extern "C" void kernel_launch(void* const* d_in, const int* in_sizes, int n_in,
                              void* d_out, int out_size) {
    const float* U = (const float*)d_in[0];
    const float* P = (const float*)d_in[1];
    const float* K = (const float*)d_in[2];
    float* out = (float*)d_out;

    __nv_bfloat16 *pKb, *pKTb, *pB2T, *paTb;
    float *pC, *pKTa;
    cudaGetSymbolAddress((void**)&pKb,  g_Kb);
    cudaGetSymbolAddress((void**)&pKTb, g_KTb);
    cudaGetSymbolAddress((void**)&pB2T, g_B2T);
    cudaGetSymbolAddress((void**)&paTb, g_aTb);
    cudaGetSymbolAddress((void**)&pC,   g_C);
    cudaGetSymbolAddress((void**)&pKTa, g_KTa);

    constexpr int SMEM_B = STAGES * STG32 * 4;   // 61440 B
    cudaFuncSetAttribute(gemm_bf16,
                         cudaFuncAttributeMaxDynamicSharedMemorySize, SMEM_B);
    cudaFuncSetAttribute(gemm_bf16,
                         cudaFuncAttributePreferredSharedMemoryCarveout, 100);

    dim3 t32(32, 32);

    // 0) zero split-K accumulators
    cudaMemsetAsync(pC,   0, (size_t)NDIM * B2R  * sizeof(float), 0);
    cudaMemsetAsync(pKTa, 0, (size_t)NDIM * BDIM * sizeof(float), 0);

    // 1) K -> bf16 (both orientations); [f | f*flog]^T bf16
    kprep_kernel<<<dim3(NDIM / 32, NDIM / 32), t32>>>(K);
    prep_kernel<<<dim3(NDIM / 32, BDIM / 32), t32>>>(U);

    // 2) [Kf | K@(f*flog)] = Kb @ B2T^T    (split-K = 2 -> 512 CTAs)
    gemm_bf16<<<dim3(B2R / 128, NDIM / 128, 2), 256, SMEM_B>>>(
        pKb, pB2T, pC, B2R, 4096 / BKT / 2);

    // 3) a = P/Kf -> a^T bf16 + partials
    epi1_kernel<<<dim3(BDIM / 32, NDIM / 32), t32>>>(P);

    // 4) K^T @ a = KTb @ aTb^T             (split-K = 4 -> 512 CTAs)
    gemm_bf16<<<dim3(BDIM / 128, NDIM / 128, 4), 256, SMEM_B>>>(
        pKTb, paTb, pKTa, BDIM, 4096 / BKT / 4);

    // 5) S4 partials
    epi2_kernel<<<NDIM, 512>>>(U);

    // 6) combine
    final_kernel<<<1, 1024>>>(out);
}

// round 12
// speedup vs baseline: 1.8430x; 1.2479x over previous
#include <cuda_runtime.h>
#include <cuda_bf16.h>
#include <math.h>
#include <stdint.h>

#define NDIM  4096
#define BDIM  512
#define B2R   1024
#define EPSV  1.0f
#define LAMDA 10.0f

// ---------------- scratch (static device globals; no allocation) -------------
__device__ __nv_bfloat16 g_Kb [NDIM * NDIM];   // K bf16 [m][k] (only copy of K)
__device__ __nv_bfloat16 g_B2T[B2R  * NDIM];   // [f | f*flog]^T bf16 [n][k]
__device__ __nv_bfloat16 g_aTb[BDIM * NDIM];   // a^T bf16 [n][k]
__device__ float g_C  [NDIM * B2R ];           // [4096][1024]: Kf | K@(f*flog)
__device__ float g_KTa[NDIM * BDIM];           // K^T @ a [4096][512]
__device__ float g_r1[2048], g_r2[2048], g_r3[2048];
__device__ float g_p4[NDIM];

// ---------------- helpers -----------------------------------------------------
__device__ __forceinline__ uint32_t smem_u32(const void* p) {
    return (uint32_t)__cvta_generic_to_shared(p);
}
__device__ __forceinline__ void cpasync16(uint32_t dst, const void* src) {
    asm volatile("cp.async.cg.shared.global [%0], [%1], 16;"
                 :: "r"(dst), "l"(src) : "memory");
}
__device__ __forceinline__ void mma_bf16(float* c, const uint32_t* a, const uint32_t* b) {
    asm volatile(
        "mma.sync.aligned.m16n8k16.row.col.f32.bf16.bf16.f32 "
        "{%0,%1,%2,%3}, {%4,%5,%6,%7}, {%8,%9}, {%0,%1,%2,%3};"
        : "+f"(c[0]), "+f"(c[1]), "+f"(c[2]), "+f"(c[3])
        : "r"(a[0]), "r"(a[1]), "r"(a[2]), "r"(a[3]), "r"(b[0]), "r"(b[1]));
}
__device__ __forceinline__ void ldsm4(uint32_t& r0, uint32_t& r1, uint32_t& r2,
                                      uint32_t& r3, uint32_t addr) {
    asm volatile("ldmatrix.sync.aligned.m8n8.x4.shared.b16 {%0,%1,%2,%3}, [%4];"
                 : "=r"(r0), "=r"(r1), "=r"(r2), "=r"(r3) : "r"(addr));
}
__device__ __forceinline__ void ldsm4t(uint32_t& r0, uint32_t& r1, uint32_t& r2,
                                       uint32_t& r3, uint32_t addr) {
    asm volatile("ldmatrix.sync.aligned.m8n8.x4.trans.shared.b16 {%0,%1,%2,%3}, [%4];"
                 : "=r"(r0), "=r"(r1), "=r"(r2), "=r"(r3) : "r"(addr));
}

// ---------------- bf16 tensor-core GEMM ----------------------------------------
// C[4096 -> M][ncols] (+)= op(A) @ B^T
// TRANSA=false: A is [M][4096] bf16 row-major (m x k); tile smem [m][k] str 80B.
// TRANSA=true : op(A)=A^T with A [4096][M']... A-operand tile loaded from
//               A[k][m] rows directly, smem [k][m] str 272B, ldmatrix.trans.
// B: [ncols][4096] bf16 row-major (n x k), tile smem [n][k] str 80B.
// ATOMIC: accumulate via atomicAdd (split-K) vs plain store.
#define STAGES 3
#define BKT 32

template <bool TRANSA, bool ATOMIC>
__global__ void __launch_bounds__(256, 2)
gemm_bf16(const __nv_bfloat16* __restrict__ A, const __nv_bfloat16* __restrict__ B,
          float* __restrict__ C, int ncols, int ktiles)
{
    extern __shared__ uint32_t sm32[];
    constexpr int A_TSZ32 = TRANSA ? (32 * 68) : (128 * 20);
    constexpr int B_TSZ32 = 128 * 20;
    constexpr int STG32   = A_TSZ32 + B_TSZ32;

    const int tid  = threadIdx.x;
    const int wid  = tid >> 5, lane = tid & 31;
    const int grp  = lane >> 2, tg = lane & 3;
    const int wm   = (wid >> 2) * 64;   // 2 warps in m
    const int wn   = (wid & 3) * 32;    // 4 warps in n
    const int bm   = blockIdx.y * 128;
    const int bn   = blockIdx.x * 128;
    const int kt0  = blockIdx.z * ktiles;

    // ldmatrix lane selectors
    const int a_row = (lane & 15);                        // non-trans A
    const int a_kc  = (lane >> 4);
    const int ta_k  = (lane >> 4) * 8 + (lane & 7);       // trans A: k-row
    const int ta_m  = ((lane >> 3) & 1) * 8;              // trans A: m-col base
    const int b_row = (lane & 7) + ((lane >> 4) & 1) * 8; // B composite
    const int b_kc  = ((lane >> 3) & 1);

    float acc[4][4][4];
#pragma unroll
    for (int i = 0; i < 4; i++)
#pragma unroll
        for (int j = 0; j < 4; j++)
#pragma unroll
            for (int k = 0; k < 4; k++) acc[i][j][k] = 0.0f;

    auto load_stage = [&](int kt, int s) {
        uint32_t* As = sm32 + s * STG32;
        uint32_t* Bs = As + A_TSZ32;
        const int k0 = (kt0 + kt) * BKT;
        if (!TRANSA) {
            // A tile [m][k]: 128 rows x 32 bf16, stride 20 words
#pragma unroll
            for (int h = 0; h < 2; h++) {
                int ch = tid + h * 256;
                int r = ch >> 2, c = ch & 3;
                cpasync16(smem_u32(As + r * 20 + c * 4),
                          A + (size_t)(bm + r) * 4096 + k0 + c * 8);
            }
        } else {
            // A tile [k][m]: 32 k-rows x 128 m-cols, stride 68 words (272B)
#pragma unroll
            for (int h = 0; h < 2; h++) {
                int ch = tid + h * 256;          // 0..511
                int r = ch >> 4, c = ch & 15;    // r: k-row, c: 16B chunk
                cpasync16(smem_u32(As + r * 68 + c * 4),
                          A + (size_t)(k0 + r) * 4096 + bm + c * 8);
            }
        }
        // B tile [n][k]: 128 rows x 32 bf16, stride 20 words
#pragma unroll
        for (int h = 0; h < 2; h++) {
            int ch = tid + h * 256;
            int r = ch >> 2, c = ch & 3;
            cpasync16(smem_u32(Bs + r * 20 + c * 4),
                      B + (size_t)(bn + r) * 4096 + k0 + c * 8);
        }
        asm volatile("cp.async.commit_group;" ::: "memory");
    };

    for (int kt = 0; kt < STAGES - 1; kt++) load_stage(kt, kt);

    for (int kt = 0; kt < ktiles; kt++) {
        asm volatile("cp.async.wait_group %0;" :: "n"(STAGES - 2) : "memory");
        __syncthreads();

        int nx = kt + STAGES - 1;
        if (nx < ktiles) load_stage(nx, nx % STAGES);

        const uint32_t Asb = smem_u32(sm32 + (kt % STAGES) * STG32);
        const uint32_t Bsb = Asb + A_TSZ32 * 4;

#pragma unroll
        for (int ks = 0; ks < 2; ks++) {           // two k=16 steps
            uint32_t af[4][4], bf[4][2];
#pragma unroll
            for (int mf = 0; mf < 4; mf++) {
                if (!TRANSA) {
                    uint32_t addr = Asb + (uint32_t)(wm + mf * 16 + a_row) * 80u
                                  + (uint32_t)(ks * 2 + a_kc) * 16u;
                    ldsm4(af[mf][0], af[mf][1], af[mf][2], af[mf][3], addr);
                } else {
                    uint32_t addr = Asb + (uint32_t)(ks * 16 + ta_k) * 272u
                                  + (uint32_t)(wm + mf * 16 + ta_m) * 2u;
                    ldsm4t(af[mf][0], af[mf][1], af[mf][2], af[mf][3], addr);
                }
            }
#pragma unroll
            for (int np = 0; np < 2; np++) {
                uint32_t addr = Bsb + (uint32_t)(wn + np * 16 + b_row) * 80u
                              + (uint32_t)(ks * 2 + b_kc) * 16u;
                ldsm4(bf[2 * np][0], bf[2 * np][1],
                      bf[2 * np + 1][0], bf[2 * np + 1][1], addr);
            }
#pragma unroll
            for (int mf = 0; mf < 4; mf++)
#pragma unroll
                for (int nf = 0; nf < 4; nf++)
                    mma_bf16(acc[mf][nf], af[mf], bf[nf]);
        }
    }

    // epilogue
#pragma unroll
    for (int mf = 0; mf < 4; mf++)
#pragma unroll
        for (int nf = 0; nf < 4; nf++) {
            int row = bm + wm + mf * 16 + grp;
            int col = bn + wn + nf * 8 + 2 * tg;
            float* c0 = C + (size_t)row * ncols + col;
            float* c1 = C + (size_t)(row + 8) * ncols + col;
            if (ATOMIC) {
                atomicAdd(c0,     acc[mf][nf][0]);
                atomicAdd(c0 + 1, acc[mf][nf][1]);
                atomicAdd(c1,     acc[mf][nf][2]);
                atomicAdd(c1 + 1, acc[mf][nf][3]);
            } else {
                *reinterpret_cast<float2*>(c0) = make_float2(acc[mf][nf][0], acc[mf][nf][1]);
                *reinterpret_cast<float2*>(c1) = make_float2(acc[mf][nf][2], acc[mf][nf][3]);
            }
        }
}

// ---------------- kprep: K -> bf16 (streaming convert, no transpose) -----------
__global__ void __launch_bounds__(256) kprep_kernel(const float4* __restrict__ K) {
    size_t i = (size_t)blockIdx.x * 512 + threadIdx.x * 2;   // 2 float4 per thread
    float4 v0 = K[i], v1 = K[i + 1];
    __nv_bfloat16 o[8] = {
        __float2bfloat16(v0.x), __float2bfloat16(v0.y),
        __float2bfloat16(v0.z), __float2bfloat16(v0.w),
        __float2bfloat16(v1.x), __float2bfloat16(v1.y),
        __float2bfloat16(v1.z), __float2bfloat16(v1.w)};
    *reinterpret_cast<float4*>(g_Kb + i * 4) = *reinterpret_cast<float4*>(o);
}

// ---------------- prep: [f | f*flog]^T bf16 from U -----------------------------
__global__ void __launch_bounds__(1024) prep_kernel(const float* __restrict__ U) {
    __shared__ float fs[32][33], gs[32][33];
    int tx = threadIdx.x, ty = threadIdx.y;
    int i0 = blockIdx.x * 32, j0 = blockIdx.y * 32;
    float u    = U[(size_t)(i0 + ty) * BDIM + j0 + tx];
    float flog = LAMDA * logf(LAMDA / (LAMDA - u));
    float f    = expf(flog);
    fs[ty][tx] = f;
    gs[ty][tx] = f * flog;
    __syncthreads();
    g_B2T[(size_t)(j0 + ty)       * NDIM + i0 + tx] = __float2bfloat16(fs[tx][ty]);
    g_B2T[(size_t)(512 + j0 + ty) * NDIM + i0 + tx] = __float2bfloat16(gs[tx][ty]);
}

// ---------------- reductions ---------------------------------------------------
__device__ __forceinline__ float warp_sum(float v) {
#pragma unroll
    for (int o = 16; o > 0; o >>= 1) v += __shfl_down_sync(0xffffffffu, v, o);
    return v;
}

// ---------------- epilogue 1: a^T bf16, block partials S1,S2,S3 ----------------
__global__ void __launch_bounds__(1024) epi1_kernel(const float* __restrict__ P) {
    __shared__ float as[32][33];
    __shared__ float sh1[32], sh2[32], sh3[32];
    int tx = threadIdx.x, ty = threadIdx.y;
    int j0 = blockIdx.x * 32, i0 = blockIdx.y * 32;
    int i = i0 + ty, j = j0 + tx;

    float kf = g_C[(size_t)i * B2R + j];
    float g  = g_C[(size_t)i * B2R + 512 + j];
    float p  = P[(size_t)i * BDIM + j];
    float a  = p / kf;
    as[ty][tx] = a;

    float s1 = a * g;
    float s2 = p * (logf(p) - logf(kf));
    float s3 = p;

    int lt = ty * 32 + tx, lane = lt & 31, w = lt >> 5;
    s1 = warp_sum(s1); s2 = warp_sum(s2); s3 = warp_sum(s3);
    if (lane == 0) { sh1[w] = s1; sh2[w] = s2; sh3[w] = s3; }
    __syncthreads();

    g_aTb[(size_t)(j0 + ty) * NDIM + i0 + tx] = __float2bfloat16(as[tx][ty]);

    if (w == 0) {
        float v1 = sh1[lane], v2 = sh2[lane], v3 = sh3[lane];
        v1 = warp_sum(v1); v2 = warp_sum(v2); v3 = warp_sum(v3);
        if (lane == 0) {
            int bid = blockIdx.y * 16 + blockIdx.x;
            g_r1[bid] = v1; g_r2[bid] = v2; g_r3[bid] = v3;
        }
    }
}

// ---------------- epilogue 2: S4 = sum f*(K^T a)*(eps*flog + lamda) ------------
__global__ void __launch_bounds__(512) epi2_kernel(const float* __restrict__ U) {
    __shared__ float sh[16];
    int i = blockIdx.x, j = threadIdx.x;
    float kta  = g_KTa[(size_t)i * BDIM + j];
    float u    = U[(size_t)i * BDIM + j];
    float flog = LAMDA * logf(LAMDA / (LAMDA - u));
    float f    = expf(flog);
    float s4   = f * kta * (EPSV * flog + LAMDA);

    s4 = warp_sum(s4);
    int lane = j & 31, w = j >> 5;
    if (lane == 0) sh[w] = s4;
    __syncthreads();
    if (w == 0) {
        float v = (lane < 16) ? sh[lane] : 0.0f;
        v = warp_sum(v);
        if (lane == 0) g_p4[i] = v;
    }
}

// ---------------- final combine ------------------------------------------------
__global__ void __launch_bounds__(1024) final_kernel(float* __restrict__ out) {
    __shared__ float sh1[32], sh2[32], sh3[32], sh4[32];
    int t = threadIdx.x;
    float s1 = 0, s2 = 0, s3 = 0, s4 = 0;
    for (int i = t; i < 2048; i += 1024) { s1 += g_r1[i]; s2 += g_r2[i]; s3 += g_r3[i]; }
    for (int i = t; i < NDIM; i += 1024) s4 += g_p4[i];
    s1 = warp_sum(s1); s2 = warp_sum(s2); s3 = warp_sum(s3); s4 = warp_sum(s4);
    int lane = t & 31, w = t >> 5;
    if (lane == 0) { sh1[w] = s1; sh2[w] = s2; sh3[w] = s3; sh4[w] = s4; }
    __syncthreads();
    if (w == 0) {
        float v1 = sh1[lane], v2 = sh2[lane], v3 = sh3[lane], v4 = sh4[lane];
        v1 = warp_sum(v1); v2 = warp_sum(v2); v3 = warp_sum(v3); v4 = warp_sum(v4);
        if (lane == 0) out[0] = EPSV * (v1 + v2 - v3) - v4;
    }
}

// ---------------- launch -------------------------------------------------------
extern "C" void kernel_launch(void* const* d_in, const int* in_sizes, int n_in,
                              void* d_out, int out_size) {
    const float* U = (const float*)d_in[0];
    const float* P = (const float*)d_in[1];
    const float* K = (const float*)d_in[2];
    float* out = (float*)d_out;

    __nv_bfloat16 *pKb, *pB2T, *paTb;
    float *pC, *pKTa;
    cudaGetSymbolAddress((void**)&pKb,  g_Kb);
    cudaGetSymbolAddress((void**)&pB2T, g_B2T);
    cudaGetSymbolAddress((void**)&paTb, g_aTb);
    cudaGetSymbolAddress((void**)&pC,   g_C);
    cudaGetSymbolAddress((void**)&pKTa, g_KTa);

    constexpr int SMEM_N = STAGES * (128 * 20 + 128 * 20) * 4;  // 61440 B
    constexpr int SMEM_T = STAGES * (32 * 68 + 128 * 20) * 4;   // 56832 B
    cudaFuncSetAttribute((const void*)gemm_bf16<false, false>,
                         cudaFuncAttributeMaxDynamicSharedMemorySize, SMEM_N);
    cudaFuncSetAttribute((const void*)gemm_bf16<true, true>,
                         cudaFuncAttributeMaxDynamicSharedMemorySize, SMEM_T);
    cudaFuncSetAttribute((const void*)gemm_bf16<false, false>,
                         cudaFuncAttributePreferredSharedMemoryCarveout, 100);
    cudaFuncSetAttribute((const void*)gemm_bf16<true, true>,
                         cudaFuncAttributePreferredSharedMemoryCarveout, 100);

    dim3 t32(32, 32);

    // 0) zero split-K accumulator (GEMM2 only)
    cudaMemsetAsync(pKTa, 0, (size_t)NDIM * BDIM * sizeof(float), 0);

    // 1) K -> bf16 (single orientation); [f | f*flog]^T bf16
    kprep_kernel<<<NDIM * NDIM / 2048, 256>>>((const float4*)K);
    prep_kernel<<<dim3(NDIM / 32, BDIM / 32), t32>>>(U);

    // 2) [Kf | K@(f*flog)] = Kb @ B2T^T   (no split, plain stores; 256 CTAs)
    gemm_bf16<false, false><<<dim3(B2R / 128, NDIM / 128, 1), 256, SMEM_N>>>(
        pKb, pB2T, pC, B2R, 4096 / BKT);

    // 3) a = P/Kf -> a^T bf16 + partials
    epi1_kernel<<<dim3(BDIM / 32, NDIM / 32), t32>>>(P);

    // 4) K^T @ a = Kb^T @ aTb^T  (trans-A ldmatrix; split-K=2 -> 256 CTAs)
    gemm_bf16<true, true><<<dim3(BDIM / 128, NDIM / 128, 2), 256, SMEM_T>>>(
        pKb, paTb, pKTa, BDIM, 4096 / BKT / 2);

    // 5) S4 partials
    epi2_kernel<<<NDIM, 512>>>(U);

    // 6) combine
    final_kernel<<<1, 1024>>>(out);
}

// round 13
// speedup vs baseline: 2.3787x; 1.2907x over previous
#include <cuda_runtime.h>
#include <cuda_bf16.h>
#include <math.h>
#include <stdint.h>

#define NDIM  4096
#define BDIM  512
#define EPSV  1.0f
#define LAMDA 10.0f

// ---------------- scratch (static device globals; no allocation) -------------
__device__ __nv_bfloat16 g_Kb [NDIM * NDIM];   // K bf16 [m][k] (only copy of K)
__device__ __nv_bfloat16 g_fT [BDIM * NDIM];   // f^T bf16 [n][k]
__device__ __nv_bfloat16 g_aTb[BDIM * NDIM];   // a^T bf16 [n][k]
__device__ float g_C  [NDIM * BDIM];           // Kf      [4096][512]
__device__ float g_KTa[NDIM * BDIM];           // K^T @ a [4096][512]
__device__ float g_r2[2048], g_r3[2048];       // epi1 block partials
__device__ float g_p1[NDIM], g_p4[NDIM];       // epi2 row partials

// ---------------- helpers -----------------------------------------------------
__device__ __forceinline__ uint32_t smem_u32(const void* p) {
    return (uint32_t)__cvta_generic_to_shared(p);
}
__device__ __forceinline__ void cpasync16(uint32_t dst, const void* src) {
    asm volatile("cp.async.cg.shared.global [%0], [%1], 16;"
                 :: "r"(dst), "l"(src) : "memory");
}
__device__ __forceinline__ void mma_bf16(float* c, const uint32_t* a, const uint32_t* b) {
    asm volatile(
        "mma.sync.aligned.m16n8k16.row.col.f32.bf16.bf16.f32 "
        "{%0,%1,%2,%3}, {%4,%5,%6,%7}, {%8,%9}, {%0,%1,%2,%3};"
        : "+f"(c[0]), "+f"(c[1]), "+f"(c[2]), "+f"(c[3])
        : "r"(a[0]), "r"(a[1]), "r"(a[2]), "r"(a[3]), "r"(b[0]), "r"(b[1]));
}
__device__ __forceinline__ void ldsm4(uint32_t& r0, uint32_t& r1, uint32_t& r2,
                                      uint32_t& r3, uint32_t addr) {
    asm volatile("ldmatrix.sync.aligned.m8n8.x4.shared.b16 {%0,%1,%2,%3}, [%4];"
                 : "=r"(r0), "=r"(r1), "=r"(r2), "=r"(r3) : "r"(addr));
}
__device__ __forceinline__ void ldsm4t(uint32_t& r0, uint32_t& r1, uint32_t& r2,
                                       uint32_t& r3, uint32_t addr) {
    asm volatile("ldmatrix.sync.aligned.m8n8.x4.trans.shared.b16 {%0,%1,%2,%3}, [%4];"
                 : "=r"(r0), "=r"(r1), "=r"(r2), "=r"(r3) : "r"(addr));
}

// ---------------- bf16 tensor-core GEMM (split-K, atomic accumulate) -----------
// C[4096][512] += op(A) @ B^T
// TRANSA=false: A [4096][4096] bf16 (m x k); tile smem [m][k] stride 80B.
// TRANSA=true : op(A)=A^T; tiles loaded from A[k][m] rows, smem [k][m] stride
//               272B, fragments via ldmatrix.trans.
// B: [512][4096] bf16 (n x k), tile smem [n][k] stride 80B.
#define STAGES 3
#define BKT 32

template <bool TRANSA>
__global__ void __launch_bounds__(256, 2)
gemm_bf16(const __nv_bfloat16* __restrict__ A, const __nv_bfloat16* __restrict__ B,
          float* __restrict__ C, int ncols, int ktiles)
{
    extern __shared__ uint32_t sm32[];
    constexpr int A_TSZ32 = TRANSA ? (32 * 68) : (128 * 20);
    constexpr int B_TSZ32 = 128 * 20;
    constexpr int STG32   = A_TSZ32 + B_TSZ32;

    const int tid  = threadIdx.x;
    const int wid  = tid >> 5, lane = tid & 31;
    const int grp  = lane >> 2, tg = lane & 3;
    const int wm   = (wid >> 2) * 64;   // 2 warps in m
    const int wn   = (wid & 3) * 32;    // 4 warps in n
    const int bm   = blockIdx.y * 128;
    const int bn   = blockIdx.x * 128;
    const int kt0  = blockIdx.z * ktiles;

    // ldmatrix lane selectors
    const int a_row = (lane & 15);                        // non-trans A
    const int a_kc  = (lane >> 4);
    const int ta_k  = (lane >> 4) * 8 + (lane & 7);       // trans A: k-row
    const int ta_m  = ((lane >> 3) & 1) * 8;              // trans A: m-col base
    const int b_row = (lane & 7) + ((lane >> 4) & 1) * 8; // B composite
    const int b_kc  = ((lane >> 3) & 1);

    float acc[4][4][4];
#pragma unroll
    for (int i = 0; i < 4; i++)
#pragma unroll
        for (int j = 0; j < 4; j++)
#pragma unroll
            for (int k = 0; k < 4; k++) acc[i][j][k] = 0.0f;

    auto load_stage = [&](int kt, int s) {
        uint32_t* As = sm32 + s * STG32;
        uint32_t* Bs = As + A_TSZ32;
        const int k0 = (kt0 + kt) * BKT;
        if (!TRANSA) {
#pragma unroll
            for (int h = 0; h < 2; h++) {
                int ch = tid + h * 256;
                int r = ch >> 2, c = ch & 3;
                cpasync16(smem_u32(As + r * 20 + c * 4),
                          A + (size_t)(bm + r) * 4096 + k0 + c * 8);
            }
        } else {
#pragma unroll
            for (int h = 0; h < 2; h++) {
                int ch = tid + h * 256;
                int r = ch >> 4, c = ch & 15;
                cpasync16(smem_u32(As + r * 68 + c * 4),
                          A + (size_t)(k0 + r) * 4096 + bm + c * 8);
            }
        }
#pragma unroll
        for (int h = 0; h < 2; h++) {
            int ch = tid + h * 256;
            int r = ch >> 2, c = ch & 3;
            cpasync16(smem_u32(Bs + r * 20 + c * 4),
                      B + (size_t)(bn + r) * 4096 + k0 + c * 8);
        }
        asm volatile("cp.async.commit_group;" ::: "memory");
    };

    for (int kt = 0; kt < STAGES - 1; kt++) load_stage(kt, kt);

    for (int kt = 0; kt < ktiles; kt++) {
        asm volatile("cp.async.wait_group %0;" :: "n"(STAGES - 2) : "memory");
        __syncthreads();

        int nx = kt + STAGES - 1;
        if (nx < ktiles) load_stage(nx, nx % STAGES);

        const uint32_t Asb = smem_u32(sm32 + (kt % STAGES) * STG32);
        const uint32_t Bsb = Asb + A_TSZ32 * 4;

#pragma unroll
        for (int ks = 0; ks < 2; ks++) {           // two k=16 steps
            uint32_t af[4][4], bf[4][2];
#pragma unroll
            for (int mf = 0; mf < 4; mf++) {
                if (!TRANSA) {
                    uint32_t addr = Asb + (uint32_t)(wm + mf * 16 + a_row) * 80u
                                  + (uint32_t)(ks * 2 + a_kc) * 16u;
                    ldsm4(af[mf][0], af[mf][1], af[mf][2], af[mf][3], addr);
                } else {
                    uint32_t addr = Asb + (uint32_t)(ks * 16 + ta_k) * 272u
                                  + (uint32_t)(wm + mf * 16 + ta_m) * 2u;
                    ldsm4t(af[mf][0], af[mf][1], af[mf][2], af[mf][3], addr);
                }
            }
#pragma unroll
            for (int np = 0; np < 2; np++) {
                uint32_t addr = Bsb + (uint32_t)(wn + np * 16 + b_row) * 80u
                              + (uint32_t)(ks * 2 + b_kc) * 16u;
                ldsm4(bf[2 * np][0], bf[2 * np][1],
                      bf[2 * np + 1][0], bf[2 * np + 1][1], addr);
            }
#pragma unroll
            for (int mf = 0; mf < 4; mf++)
#pragma unroll
                for (int nf = 0; nf < 4; nf++)
                    mma_bf16(acc[mf][nf], af[mf], bf[nf]);
        }
    }

    // epilogue: accumulate this split's partial into C
#pragma unroll
    for (int mf = 0; mf < 4; mf++)
#pragma unroll
        for (int nf = 0; nf < 4; nf++) {
            int row = bm + wm + mf * 16 + grp;
            int col = bn + wn + nf * 8 + 2 * tg;
            float* c0 = C + (size_t)row * ncols + col;
            float* c1 = C + (size_t)(row + 8) * ncols + col;
            atomicAdd(c0,     acc[mf][nf][0]);
            atomicAdd(c0 + 1, acc[mf][nf][1]);
            atomicAdd(c1,     acc[mf][nf][2]);
            atomicAdd(c1 + 1, acc[mf][nf][3]);
        }
}

// ---------------- kprep: K -> bf16 (streaming convert) -------------------------
__global__ void __launch_bounds__(256) kprep_kernel(const float4* __restrict__ K) {
    size_t i = (size_t)blockIdx.x * 512 + threadIdx.x * 2;   // 2 float4 per thread
    float4 v0 = K[i], v1 = K[i + 1];
    __nv_bfloat16 o[8] = {
        __float2bfloat16(v0.x), __float2bfloat16(v0.y),
        __float2bfloat16(v0.z), __float2bfloat16(v0.w),
        __float2bfloat16(v1.x), __float2bfloat16(v1.y),
        __float2bfloat16(v1.z), __float2bfloat16(v1.w)};
    *reinterpret_cast<float4*>(g_Kb + i * 4) = *reinterpret_cast<float4*>(o);
}

// ---------------- prep: f^T bf16 from U ----------------------------------------
__global__ void __launch_bounds__(1024) prep_kernel(const float* __restrict__ U) {
    __shared__ float fs[32][33];
    int tx = threadIdx.x, ty = threadIdx.y;
    int i0 = blockIdx.x * 32, j0 = blockIdx.y * 32;
    float u    = U[(size_t)(i0 + ty) * BDIM + j0 + tx];
    float flog = LAMDA * logf(LAMDA / (LAMDA - u));
    fs[ty][tx] = expf(flog);
    __syncthreads();
    g_fT[(size_t)(j0 + ty) * NDIM + i0 + tx] = __float2bfloat16(fs[tx][ty]);
}

// ---------------- reductions ---------------------------------------------------
__device__ __forceinline__ float warp_sum(float v) {
#pragma unroll
    for (int o = 16; o > 0; o >>= 1) v += __shfl_down_sync(0xffffffffu, v, o);
    return v;
}

// ---------------- epilogue 1: a^T bf16, block partials S2, S3 ------------------
__global__ void __launch_bounds__(1024) epi1_kernel(const float* __restrict__ P) {
    __shared__ float as[32][33];
    __shared__ float sh2[32], sh3[32];
    int tx = threadIdx.x, ty = threadIdx.y;
    int j0 = blockIdx.x * 32, i0 = blockIdx.y * 32;
    int i = i0 + ty, j = j0 + tx;

    float kf = g_C[(size_t)i * BDIM + j];
    float p  = P[(size_t)i * BDIM + j];
    float a  = p / kf;
    as[ty][tx] = a;

    float s2 = p * (logf(p) - logf(kf));   // P * log(P/Kf)
    float s3 = p;

    int lt = ty * 32 + tx, lane = lt & 31, w = lt >> 5;
    s2 = warp_sum(s2); s3 = warp_sum(s3);
    if (lane == 0) { sh2[w] = s2; sh3[w] = s3; }
    __syncthreads();

    g_aTb[(size_t)(j0 + ty) * NDIM + i0 + tx] = __float2bfloat16(as[tx][ty]);

    if (w == 0) {
        float v2 = sh2[lane], v3 = sh3[lane];
        v2 = warp_sum(v2); v3 = warp_sum(v3);
        if (lane == 0) {
            int bid = blockIdx.y * 16 + blockIdx.x;
            g_r2[bid] = v2; g_r3[bid] = v3;
        }
    }
}

// ---------------- epilogue 2: S1 = sum f*flog*kta ; S4 = sum f*kta*(eps*flog+lamda)
__global__ void __launch_bounds__(512) epi2_kernel(const float* __restrict__ U) {
    __shared__ float sh1[16], sh4[16];
    int i = blockIdx.x, j = threadIdx.x;
    float kta  = g_KTa[(size_t)i * BDIM + j];
    float u    = U[(size_t)i * BDIM + j];
    float flog = LAMDA * logf(LAMDA / (LAMDA - u));
    float f    = expf(flog);
    float fk   = f * kta;
    float s1   = fk * flog;                    // (f*flog) . (K^T a)  == term1
    float s4   = fk * (EPSV * flog + LAMDA);   // lamda*KL part (negated later)

    s1 = warp_sum(s1); s4 = warp_sum(s4);
    int lane = j & 31, w = j >> 5;
    if (lane == 0) { sh1[w] = s1; sh4[w] = s4; }
    __syncthreads();
    if (w == 0) {
        float v1 = (lane < 16) ? sh1[lane] : 0.0f;
        float v4 = (lane < 16) ? sh4[lane] : 0.0f;
        v1 = warp_sum(v1); v4 = warp_sum(v4);
        if (lane == 0) { g_p1[i] = v1; g_p4[i] = v4; }
    }
}

// ---------------- final combine ------------------------------------------------
__global__ void __launch_bounds__(1024) final_kernel(float* __restrict__ out) {
    __shared__ float sh1[32], sh2[32], sh3[32], sh4[32];
    int t = threadIdx.x;
    float s1 = 0, s2 = 0, s3 = 0, s4 = 0;
    for (int i = t; i < 2048; i += 1024) { s2 += g_r2[i]; s3 += g_r3[i]; }
    for (int i = t; i < NDIM; i += 1024) { s1 += g_p1[i]; s4 += g_p4[i]; }
    s1 = warp_sum(s1); s2 = warp_sum(s2); s3 = warp_sum(s3); s4 = warp_sum(s4);
    int lane = t & 31, w = t >> 5;
    if (lane == 0) { sh1[w] = s1; sh2[w] = s2; sh3[w] = s3; sh4[w] = s4; }
    __syncthreads();
    if (w == 0) {
        float v1 = sh1[lane], v2 = sh2[lane], v3 = sh3[lane], v4 = sh4[lane];
        v1 = warp_sum(v1); v2 = warp_sum(v2); v3 = warp_sum(v3); v4 = warp_sum(v4);
        if (lane == 0) out[0] = EPSV * (v1 + v2 - v3) - v4;
    }
}

// ---------------- launch -------------------------------------------------------
extern "C" void kernel_launch(void* const* d_in, const int* in_sizes, int n_in,
                              void* d_out, int out_size) {
    const float* U = (const float*)d_in[0];
    const float* P = (const float*)d_in[1];
    const float* K = (const float*)d_in[2];
    float* out = (float*)d_out;

    __nv_bfloat16 *pKb, *pfT, *paTb;
    float *pC, *pKTa;
    cudaGetSymbolAddress((void**)&pKb,  g_Kb);
    cudaGetSymbolAddress((void**)&pfT,  g_fT);
    cudaGetSymbolAddress((void**)&paTb, g_aTb);
    cudaGetSymbolAddress((void**)&pC,   g_C);
    cudaGetSymbolAddress((void**)&pKTa, g_KTa);

    constexpr int SMEM_N = STAGES * (128 * 20 + 128 * 20) * 4;  // 61440 B
    constexpr int SMEM_T = STAGES * (32 * 68 + 128 * 20) * 4;   // 56832 B
    cudaFuncSetAttribute((const void*)gemm_bf16<false>,
                         cudaFuncAttributeMaxDynamicSharedMemorySize, SMEM_N);
    cudaFuncSetAttribute((const void*)gemm_bf16<true>,
                         cudaFuncAttributeMaxDynamicSharedMemorySize, SMEM_T);
    cudaFuncSetAttribute((const void*)gemm_bf16<false>,
                         cudaFuncAttributePreferredSharedMemoryCarveout, 100);
    cudaFuncSetAttribute((const void*)gemm_bf16<true>,
                         cudaFuncAttributePreferredSharedMemoryCarveout, 100);

    dim3 t32(32, 32);

    // 0) zero split-K accumulators (8MB each)
    cudaMemsetAsync(pC,   0, (size_t)NDIM * BDIM * sizeof(float), 0);
    cudaMemsetAsync(pKTa, 0, (size_t)NDIM * BDIM * sizeof(float), 0);

    // 1) K -> bf16; f^T bf16
    kprep_kernel<<<NDIM * NDIM / 2048, 256>>>((const float4*)K);
    prep_kernel<<<dim3(NDIM / 32, BDIM / 32), t32>>>(U);

    // 2) Kf = Kb @ fT^T            (split-K=2 -> 256 CTAs)
    gemm_bf16<false><<<dim3(BDIM / 128, NDIM / 128, 2), 256, SMEM_N>>>(
        pKb, pfT, pC, BDIM, 4096 / BKT / 2);

    // 3) a = P/Kf -> a^T bf16 + S2,S3 partials
    epi1_kernel<<<dim3(BDIM / 32, NDIM / 32), t32>>>(P);

    // 4) K^T @ a = Kb^T @ aTb^T    (trans-A ldmatrix; split-K=2 -> 256 CTAs)
    gemm_bf16<true><<<dim3(BDIM / 128, NDIM / 128, 2), 256, SMEM_T>>>(
        pKb, paTb, pKTa, BDIM, 4096 / BKT / 2);

    // 5) S1, S4 partials
    epi2_kernel<<<NDIM, 512>>>(U);

    // 6) combine
    final_kernel<<<1, 1024>>>(out);
}

// round 14
// speedup vs baseline: 2.4304x; 1.0217x over previous
#include <cuda_runtime.h>
#include <cuda_bf16.h>
#include <math.h>
#include <stdint.h>

#define NDIM  4096
#define BDIM  512
#define EPSV  1.0f
#define LAMDA 10.0f

// ---------------- scratch (static device globals; no allocation) -------------
__device__ __nv_bfloat16 g_Kb [NDIM * NDIM];   // K bf16 [m][k] (only copy of K)
__device__ __nv_bfloat16 g_fT [BDIM * NDIM];   // f^T bf16 [n][k]
__device__ __nv_bfloat16 g_aTb[BDIM * NDIM];   // a^T bf16 [n][k]
__device__ float g_C  [NDIM * BDIM];           // Kf      [4096][512]
__device__ float g_KTa[NDIM * BDIM];           // K^T @ a [4096][512]
__device__ float g_r2[2048], g_r3[2048];       // epi1 block partials
__device__ float g_p1[NDIM], g_p4[NDIM];       // epi2 row partials

// ---------------- helpers -----------------------------------------------------
__device__ __forceinline__ uint32_t smem_u32(const void* p) {
    return (uint32_t)__cvta_generic_to_shared(p);
}
__device__ __forceinline__ void cpasync16(uint32_t dst, const void* src) {
    asm volatile("cp.async.cg.shared.global [%0], [%1], 16;"
                 :: "r"(dst), "l"(src) : "memory");
}
__device__ __forceinline__ void mma_bf16(float* c, const uint32_t* a, const uint32_t* b) {
    asm volatile(
        "mma.sync.aligned.m16n8k16.row.col.f32.bf16.bf16.f32 "
        "{%0,%1,%2,%3}, {%4,%5,%6,%7}, {%8,%9}, {%0,%1,%2,%3};"
        : "+f"(c[0]), "+f"(c[1]), "+f"(c[2]), "+f"(c[3])
        : "r"(a[0]), "r"(a[1]), "r"(a[2]), "r"(a[3]), "r"(b[0]), "r"(b[1]));
}
__device__ __forceinline__ void ldsm4(uint32_t& r0, uint32_t& r1, uint32_t& r2,
                                      uint32_t& r3, uint32_t addr) {
    asm volatile("ldmatrix.sync.aligned.m8n8.x4.shared.b16 {%0,%1,%2,%3}, [%4];"
                 : "=r"(r0), "=r"(r1), "=r"(r2), "=r"(r3) : "r"(addr));
}
__device__ __forceinline__ void ldsm4t(uint32_t& r0, uint32_t& r1, uint32_t& r2,
                                       uint32_t& r3, uint32_t addr) {
    asm volatile("ldmatrix.sync.aligned.m8n8.x4.trans.shared.b16 {%0,%1,%2,%3}, [%4];"
                 : "=r"(r0), "=r"(r1), "=r"(r2), "=r"(r3) : "r"(addr));
}

// ---------------- bf16 tensor-core GEMM (split-K, atomic accumulate) -----------
#define STAGES 3
#define BKT 32

template <bool TRANSA>
__global__ void __launch_bounds__(256, 2)
gemm_bf16(const __nv_bfloat16* __restrict__ A, const __nv_bfloat16* __restrict__ B,
          float* __restrict__ C, int ncols, int ktiles)
{
    extern __shared__ uint32_t sm32[];
    constexpr int A_TSZ32 = TRANSA ? (32 * 68) : (128 * 20);
    constexpr int B_TSZ32 = 128 * 20;
    constexpr int STG32   = A_TSZ32 + B_TSZ32;

    const int tid  = threadIdx.x;
    const int wid  = tid >> 5, lane = tid & 31;
    const int grp  = lane >> 2, tg = lane & 3;
    const int wm   = (wid >> 2) * 64;   // 2 warps in m
    const int wn   = (wid & 3) * 32;    // 4 warps in n
    const int bm   = blockIdx.y * 128;
    const int bn   = blockIdx.x * 128;
    const int kt0  = blockIdx.z * ktiles;

    const int a_row = (lane & 15);
    const int a_kc  = (lane >> 4);
    const int ta_k  = (lane >> 4) * 8 + (lane & 7);
    const int ta_m  = ((lane >> 3) & 1) * 8;
    const int b_row = (lane & 7) + ((lane >> 4) & 1) * 8;
    const int b_kc  = ((lane >> 3) & 1);

    float acc[4][4][4];
#pragma unroll
    for (int i = 0; i < 4; i++)
#pragma unroll
        for (int j = 0; j < 4; j++)
#pragma unroll
            for (int k = 0; k < 4; k++) acc[i][j][k] = 0.0f;

    auto load_stage = [&](int kt, int s) {
        uint32_t* As = sm32 + s * STG32;
        uint32_t* Bs = As + A_TSZ32;
        const int k0 = (kt0 + kt) * BKT;
        if (!TRANSA) {
#pragma unroll
            for (int h = 0; h < 2; h++) {
                int ch = tid + h * 256;
                int r = ch >> 2, c = ch & 3;
                cpasync16(smem_u32(As + r * 20 + c * 4),
                          A + (size_t)(bm + r) * 4096 + k0 + c * 8);
            }
        } else {
#pragma unroll
            for (int h = 0; h < 2; h++) {
                int ch = tid + h * 256;
                int r = ch >> 4, c = ch & 15;
                cpasync16(smem_u32(As + r * 68 + c * 4),
                          A + (size_t)(k0 + r) * 4096 + bm + c * 8);
            }
        }
#pragma unroll
        for (int h = 0; h < 2; h++) {
            int ch = tid + h * 256;
            int r = ch >> 2, c = ch & 3;
            cpasync16(smem_u32(Bs + r * 20 + c * 4),
                      B + (size_t)(bn + r) * 4096 + k0 + c * 8);
        }
        asm volatile("cp.async.commit_group;" ::: "memory");
    };

    for (int kt = 0; kt < STAGES - 1; kt++) load_stage(kt, kt);

    for (int kt = 0; kt < ktiles; kt++) {
        asm volatile("cp.async.wait_group %0;" :: "n"(STAGES - 2) : "memory");
        __syncthreads();

        int nx = kt + STAGES - 1;
        if (nx < ktiles) load_stage(nx, nx % STAGES);

        const uint32_t Asb = smem_u32(sm32 + (kt % STAGES) * STG32);
        const uint32_t Bsb = Asb + A_TSZ32 * 4;

#pragma unroll
        for (int ks = 0; ks < 2; ks++) {
            uint32_t af[4][4], bf[4][2];
#pragma unroll
            for (int mf = 0; mf < 4; mf++) {
                if (!TRANSA) {
                    uint32_t addr = Asb + (uint32_t)(wm + mf * 16 + a_row) * 80u
                                  + (uint32_t)(ks * 2 + a_kc) * 16u;
                    ldsm4(af[mf][0], af[mf][1], af[mf][2], af[mf][3], addr);
                } else {
                    uint32_t addr = Asb + (uint32_t)(ks * 16 + ta_k) * 272u
                                  + (uint32_t)(wm + mf * 16 + ta_m) * 2u;
                    ldsm4t(af[mf][0], af[mf][1], af[mf][2], af[mf][3], addr);
                }
            }
#pragma unroll
            for (int np = 0; np < 2; np++) {
                uint32_t addr = Bsb + (uint32_t)(wn + np * 16 + b_row) * 80u
                              + (uint32_t)(ks * 2 + b_kc) * 16u;
                ldsm4(bf[2 * np][0], bf[2 * np][1],
                      bf[2 * np + 1][0], bf[2 * np + 1][1], addr);
            }
#pragma unroll
            for (int mf = 0; mf < 4; mf++)
#pragma unroll
                for (int nf = 0; nf < 4; nf++)
                    mma_bf16(acc[mf][nf], af[mf], bf[nf]);
        }
    }

#pragma unroll
    for (int mf = 0; mf < 4; mf++)
#pragma unroll
        for (int nf = 0; nf < 4; nf++) {
            int row = bm + wm + mf * 16 + grp;
            int col = bn + wn + nf * 8 + 2 * tg;
            float* c0 = C + (size_t)row * ncols + col;
            float* c1 = C + (size_t)(row + 8) * ncols + col;
            atomicAdd(c0,     acc[mf][nf][0]);
            atomicAdd(c0 + 1, acc[mf][nf][1]);
            atomicAdd(c1,     acc[mf][nf][2]);
            atomicAdd(c1 + 1, acc[mf][nf][3]);
        }
}

// ---------------- kprep: K -> bf16 (streaming convert) -------------------------
__global__ void __launch_bounds__(256) kprep_kernel(const float4* __restrict__ K) {
    size_t i = (size_t)blockIdx.x * 512 + threadIdx.x * 2;
    float4 v0 = K[i], v1 = K[i + 1];
    __nv_bfloat16 o[8] = {
        __float2bfloat16(v0.x), __float2bfloat16(v0.y),
        __float2bfloat16(v0.z), __float2bfloat16(v0.w),
        __float2bfloat16(v1.x), __float2bfloat16(v1.y),
        __float2bfloat16(v1.z), __float2bfloat16(v1.w)};
    *reinterpret_cast<float4*>(g_Kb + i * 4) = *reinterpret_cast<float4*>(o);
}

// ---------------- prep: f^T bf16 from U (fast math) ----------------------------
__global__ void __launch_bounds__(1024) prep_kernel(const float* __restrict__ U) {
    __shared__ float fs[32][33];
    int tx = threadIdx.x, ty = threadIdx.y;
    int i0 = blockIdx.x * 32, j0 = blockIdx.y * 32;
    float u    = U[(size_t)(i0 + ty) * BDIM + j0 + tx];
    float flog = LAMDA * __logf(__fdividef(LAMDA, LAMDA - u));
    fs[ty][tx] = __expf(flog);
    __syncthreads();
    g_fT[(size_t)(j0 + ty) * NDIM + i0 + tx] = __float2bfloat16(fs[tx][ty]);
}

// ---------------- reductions ---------------------------------------------------
__device__ __forceinline__ float warp_sum(float v) {
#pragma unroll
    for (int o = 16; o > 0; o >>= 1) v += __shfl_down_sync(0xffffffffu, v, o);
    return v;
}

// ---------------- epilogue 1: a^T bf16, block partials S2, S3 (fast math) ------
__global__ void __launch_bounds__(1024) epi1_kernel(const float* __restrict__ P) {
    __shared__ float as[32][33];
    __shared__ float sh2[32], sh3[32];
    int tx = threadIdx.x, ty = threadIdx.y;
    int j0 = blockIdx.x * 32, i0 = blockIdx.y * 32;
    int i = i0 + ty, j = j0 + tx;

    float kf = g_C[(size_t)i * BDIM + j];
    float p  = P[(size_t)i * BDIM + j];
    float a  = __fdividef(p, kf);
    as[ty][tx] = a;

    float s2 = p * __logf(a);   // p * log(p/Kf)  -- one log instead of two
    float s3 = p;

    int lt = ty * 32 + tx, lane = lt & 31, w = lt >> 5;
    s2 = warp_sum(s2); s3 = warp_sum(s3);
    if (lane == 0) { sh2[w] = s2; sh3[w] = s3; }
    __syncthreads();

    g_aTb[(size_t)(j0 + ty) * NDIM + i0 + tx] = __float2bfloat16(as[tx][ty]);

    if (w == 0) {
        float v2 = sh2[lane], v3 = sh3[lane];
        v2 = warp_sum(v2); v3 = warp_sum(v3);
        if (lane == 0) {
            int bid = blockIdx.y * 16 + blockIdx.x;
            g_r2[bid] = v2; g_r3[bid] = v3;
        }
    }
}

// ---------------- epilogue 2: S1, S4 (fast math) -------------------------------
__global__ void __launch_bounds__(512) epi2_kernel(const float* __restrict__ U) {
    __shared__ float sh1[16], sh4[16];
    int i = blockIdx.x, j = threadIdx.x;
    float kta  = g_KTa[(size_t)i * BDIM + j];
    float u    = U[(size_t)i * BDIM + j];
    float flog = LAMDA * __logf(__fdividef(LAMDA, LAMDA - u));
    float f    = __expf(flog);
    float fk   = f * kta;
    float s1   = fk * flog;                    // (f*flog) . (K^T a) == term1
    float s4   = fk * (EPSV * flog + LAMDA);

    s1 = warp_sum(s1); s4 = warp_sum(s4);
    int lane = j & 31, w = j >> 5;
    if (lane == 0) { sh1[w] = s1; sh4[w] = s4; }
    __syncthreads();
    if (w == 0) {
        float v1 = (lane < 16) ? sh1[lane] : 0.0f;
        float v4 = (lane < 16) ? sh4[lane] : 0.0f;
        v1 = warp_sum(v1); v4 = warp_sum(v4);
        if (lane == 0) { g_p1[i] = v1; g_p4[i] = v4; }
    }
}

// ---------------- final combine ------------------------------------------------
__global__ void __launch_bounds__(1024) final_kernel(float* __restrict__ out) {
    __shared__ float sh1[32], sh2[32], sh3[32], sh4[32];
    int t = threadIdx.x;
    float s1 = 0, s2 = 0, s3 = 0, s4 = 0;
    for (int i = t; i < 2048; i += 1024) { s2 += g_r2[i]; s3 += g_r3[i]; }
    for (int i = t; i < NDIM; i += 1024) { s1 += g_p1[i]; s4 += g_p4[i]; }
    s1 = warp_sum(s1); s2 = warp_sum(s2); s3 = warp_sum(s3); s4 = warp_sum(s4);
    int lane = t & 31, w = t >> 5;
    if (lane == 0) { sh1[w] = s1; sh2[w] = s2; sh3[w] = s3; sh4[w] = s4; }
    __syncthreads();
    if (w == 0) {
        float v1 = sh1[lane], v2 = sh2[lane], v3 = sh3[lane], v4 = sh4[lane];
        v1 = warp_sum(v1); v2 = warp_sum(v2); v3 = warp_sum(v3); v4 = warp_sum(v4);
        if (lane == 0) out[0] = EPSV * (v1 + v2 - v3) - v4;
    }
}

// ---------------- launch -------------------------------------------------------
extern "C" void kernel_launch(void* const* d_in, const int* in_sizes, int n_in,
                              void* d_out, int out_size) {
    const float* U = (const float*)d_in[0];
    const float* P = (const float*)d_in[1];
    const float* K = (const float*)d_in[2];
    float* out = (float*)d_out;

    __nv_bfloat16 *pKb, *pfT, *paTb;
    float *pC, *pKTa;
    cudaGetSymbolAddress((void**)&pKb,  g_Kb);
    cudaGetSymbolAddress((void**)&pfT,  g_fT);
    cudaGetSymbolAddress((void**)&paTb, g_aTb);
    cudaGetSymbolAddress((void**)&pC,   g_C);
    cudaGetSymbolAddress((void**)&pKTa, g_KTa);

    constexpr int SMEM_N = STAGES * (128 * 20 + 128 * 20) * 4;  // 61440 B
    constexpr int SMEM_T = STAGES * (32 * 68 + 128 * 20) * 4;   // 56832 B
    cudaFuncSetAttribute((const void*)gemm_bf16<false>,
                         cudaFuncAttributeMaxDynamicSharedMemorySize, SMEM_N);
    cudaFuncSetAttribute((const void*)gemm_bf16<true>,
                         cudaFuncAttributeMaxDynamicSharedMemorySize, SMEM_T);
    cudaFuncSetAttribute((const void*)gemm_bf16<false>,
                         cudaFuncAttributePreferredSharedMemoryCarveout, 100);
    cudaFuncSetAttribute((const void*)gemm_bf16<true>,
                         cudaFuncAttributePreferredSharedMemoryCarveout, 100);

    dim3 t32(32, 32);

    // 0) zero split-K accumulators
    cudaMemsetAsync(pC,   0, (size_t)NDIM * BDIM * sizeof(float), 0);
    cudaMemsetAsync(pKTa, 0, (size_t)NDIM * BDIM * sizeof(float), 0);

    // 1) K -> bf16; f^T bf16
    kprep_kernel<<<NDIM * NDIM / 2048, 256>>>((const float4*)K);
    prep_kernel<<<dim3(NDIM / 32, BDIM / 32), t32>>>(U);

    // 2) Kf = Kb @ fT^T            (split-K=2 -> 256 CTAs)
    gemm_bf16<false><<<dim3(BDIM / 128, NDIM / 128, 2), 256, SMEM_N>>>(
        pKb, pfT, pC, BDIM, 4096 / BKT / 2);

    // 3) a = P/Kf -> a^T bf16 + S2,S3 partials
    epi1_kernel<<<dim3(BDIM / 32, NDIM / 32), t32>>>(P);

    // 4) K^T @ a = Kb^T @ aTb^T    (trans-A ldmatrix; split-K=2 -> 256 CTAs)
    gemm_bf16<true><<<dim3(BDIM / 128, NDIM / 128, 2), 256, SMEM_T>>>(
        pKb, paTb, pKTa, BDIM, 4096 / BKT / 2);

    // 5) S1, S4 partials
    epi2_kernel<<<NDIM, 512>>>(U);

    // 6) combine
    final_kernel<<<1, 1024>>>(out);
}